// round 1
// baseline (speedup 1.0000x reference)
#include <cuda_runtime.h>

namespace {
constexpr int B = 16, S = 512, HID = 512, NH = 8, DK = 64, TH = 32, TE = 16;
constexpr int BH = B * NH;            // 128
constexpr float SCALE = 0.125f;       // dk^-0.5, dk=64
}

// ---------------- scratch (device globals; no runtime allocation) -------------
__device__ float g_Qh[BH * S * DK];
__device__ float g_Kh[BH * S * DK];
__device__ float g_Vh[BH * S * DK];
__device__ float g_QHop[BH * S * TH];
__device__ float g_KHop[BH * S * TH];
__device__ float g_EB[BH * S * TE];                 // QEdge + KEdge (both row-indexed)
__device__ float g_Attn[(size_t)BH * S * S];        // 134 MB
__device__ float g_BinsH[BH * S * TH];
__device__ float g_BinsE[BH * S * TE];
__device__ float g_OutH[BH * S * DK];

// ---------------- GEMM: C = A @ W^T + bias  (512-deep) -----------------------
// TGT 0/1/2: A row-major [8192,512]; write head-layout into g_Qh/g_Kh/g_Vh.
// TGT 3:     A = g_OutH in head layout; write row-major into Cout (d_out).
template <int TGT>
__global__ __launch_bounds__(256) void gemm512_kernel(
    const float* __restrict__ A, const float* __restrict__ W,
    const float* __restrict__ bias, float* __restrict__ Cout) {
  __shared__ float As[64][33];
  __shared__ float Ws[64][33];
  const int m0 = blockIdx.y * 64, n0 = blockIdx.x * 64;
  const int tid = threadIdx.x;
  const int tx = tid & 15, ty = tid >> 4;
  float acc[4][4] = {};

  for (int k0 = 0; k0 < 512; k0 += 32) {
    for (int idx = tid; idx < 64 * 32; idx += 256) {
      const int r = idx >> 5, c = idx & 31;
      float av;
      if (TGT < 3) {
        av = A[(m0 + r) * 512 + k0 + c];
      } else {
        const int n = m0 + r, cc = k0 + c;
        const int bb = n >> 9, ii = n & 511, h = cc >> 6, d = cc & 63;
        av = g_OutH[(((bb * NH + h) * S) + ii) * DK + d];
      }
      As[r][c] = av;
      Ws[r][c] = W[(n0 + r) * 512 + k0 + c];
    }
    __syncthreads();
#pragma unroll
    for (int k = 0; k < 32; k++) {
      float a[4], w[4];
#pragma unroll
      for (int i = 0; i < 4; i++) a[i] = As[ty * 4 + i][k];
#pragma unroll
      for (int j = 0; j < 4; j++) w[j] = Ws[tx * 4 + j][k];
#pragma unroll
      for (int i = 0; i < 4; i++)
#pragma unroll
        for (int j = 0; j < 4; j++) acc[i][j] += a[i] * w[j];
    }
    __syncthreads();
  }

#pragma unroll
  for (int i = 0; i < 4; i++) {
    const int n = m0 + ty * 4 + i;
#pragma unroll
    for (int j = 0; j < 4; j++) {
      const int o = n0 + tx * 4 + j;
      const float v = acc[i][j] + bias[o];
      if (TGT == 3) {
        Cout[n * 512 + o] = v;
      } else {
        const int bb = n >> 9, ii = n & 511, h = o >> 6, d = o & 63;
        const int dst = (((bb * NH + h) * S) + ii) * DK + d;
        if (TGT == 0) g_Qh[dst] = v;
        else if (TGT == 1) g_Kh[dst] = v;
        else g_Vh[dst] = v;
      }
    }
  }
}

// ---------------- bias tables -------------------------------------------------
// QHop[bh,i,t]=Qh_i.qhe[t], KHop[bh,j,t]=Kh_j.khe[t], EB[bh,i,t]=Qh_i.qee[t]+Kh_i.kee[t]
__global__ __launch_bounds__(256) void tables_kernel(
    const float* __restrict__ qhe, const float* __restrict__ qee,
    const float* __restrict__ khe, const float* __restrict__ kee) {
  __shared__ float Qs[32][DK];
  __shared__ float Ks[32][DK];
  __shared__ float qhs[TH][DK + 1];
  __shared__ float khs[TH][DK + 1];
  __shared__ float qes[TE][DK + 1];
  __shared__ float kes[TE][DK + 1];
  const int bh = blockIdx.x, h = bh % NH;
  const int i0 = blockIdx.y * 32;
  const int tid = threadIdx.x;

  for (int idx = tid; idx < 32 * DK; idx += 256) {
    const int rr = idx >> 6, d = idx & 63;
    Qs[rr][d] = g_Qh[(bh * S + i0 + rr) * DK + d];
    Ks[rr][d] = g_Kh[(bh * S + i0 + rr) * DK + d];
  }
  for (int idx = tid; idx < TH * DK; idx += 256) {
    const int t = idx >> 6, d = idx & 63;
    qhs[t][d] = qhe[t * HID + h * DK + d];
    khs[t][d] = khe[t * HID + h * DK + d];
  }
  for (int idx = tid; idx < TE * DK; idx += 256) {
    const int t = idx >> 6, d = idx & 63;
    qes[t][d] = qee[t * HID + h * DK + d];
    kes[t][d] = kee[t * HID + h * DK + d];
  }
  __syncthreads();

  for (int idx = tid; idx < 32 * TH; idx += 256) {
    const int rr = idx >> 5, t = idx & 31;
    float sq = 0.f, sk = 0.f;
#pragma unroll
    for (int d = 0; d < DK; d++) {
      sq += Qs[rr][d] * qhs[t][d];
      sk += Ks[rr][d] * khs[t][d];
    }
    g_QHop[(bh * S + i0 + rr) * TH + t] = sq;
    g_KHop[(bh * S + i0 + rr) * TH + t] = sk;
  }
  for (int idx = tid; idx < 32 * TE; idx += 256) {
    const int rr = idx >> 4, t = idx & 15;
    float sv = 0.f;
#pragma unroll
    for (int d = 0; d < DK; d++)
      sv += Qs[rr][d] * qes[t][d] + Ks[rr][d] * kes[t][d];
    g_EB[(bh * S + i0 + rr) * TE + t] = sv;
  }
}

// ---------------- fused scores + bias + softmax + type-bins -------------------
struct AttnSmem {
  float Qs[16][DK];
  float rowhop[16][TH];
  float rowedge[16][TE];
  float Ks[64][DK + 1];
  float KHs[64][TH + 1];
  float Sbuf[16][S];
  unsigned char d8[16][S];
  unsigned char e8[16][S];
  float binsH[16][TH];
  float binsE[16][TE];
  float rowinv[16];
};

__global__ __launch_bounds__(256) void attn_kernel(
    const int* __restrict__ dist, const int* __restrict__ edge) {
  extern __shared__ char smem_raw[];
  AttnSmem& sm = *reinterpret_cast<AttnSmem*>(smem_raw);
  const int bh = blockIdx.x, b = bh / NH;
  const int i0 = blockIdx.y * 16;
  const int tid = threadIdx.x;
  const int r = tid >> 4, c16 = tid & 15;

  for (int idx = tid; idx < 16 * DK; idx += 256)
    sm.Qs[idx >> 6][idx & 63] = g_Qh[(bh * S + i0 + (idx >> 6)) * DK + (idx & 63)];
  for (int idx = tid; idx < 16 * TH; idx += 256) {
    sm.rowhop[idx >> 5][idx & 31] = g_QHop[(bh * S + i0 + (idx >> 5)) * TH + (idx & 31)];
    sm.binsH[idx >> 5][idx & 31] = 0.f;
  }
  for (int idx = tid; idx < 16 * TE; idx += 256) {
    sm.rowedge[idx >> 4][idx & 15] = g_EB[(bh * S + i0 + (idx >> 4)) * TE + (idx & 15)];
    sm.binsE[idx >> 4][idx & 15] = 0.f;
  }
  for (int idx = tid; idx < 16 * S; idx += 256) {
    const int rr = idx >> 9, j = idx & 511;
    sm.d8[rr][j] = (unsigned char)dist[((size_t)b * S + i0 + rr) * S + j];
    sm.e8[rr][j] = (unsigned char)edge[((size_t)b * S + i0 + rr) * S + j];
  }
  __syncthreads();

  for (int kt = 0; kt < 8; kt++) {
    const int j0 = kt * 64;
    for (int idx = tid; idx < 64 * DK; idx += 256)
      sm.Ks[idx >> 6][idx & 63] = g_Kh[(bh * S + j0 + (idx >> 6)) * DK + (idx & 63)];
    for (int idx = tid; idx < 64 * TH; idx += 256)
      sm.KHs[idx >> 5][idx & 31] = g_KHop[(bh * S + j0 + (idx >> 5)) * TH + (idx & 31)];
    __syncthreads();

    float acc0 = 0.f, acc1 = 0.f, acc2 = 0.f, acc3 = 0.f;
#pragma unroll 16
    for (int d = 0; d < DK; d++) {
      const float qv = sm.Qs[r][d];
      acc0 += qv * sm.Ks[c16][d];
      acc1 += qv * sm.Ks[c16 + 16][d];
      acc2 += qv * sm.Ks[c16 + 32][d];
      acc3 += qv * sm.Ks[c16 + 48][d];
    }
    float acc[4] = {acc0, acc1, acc2, acc3};
#pragma unroll
    for (int jj = 0; jj < 4; jj++) {
      const int jl = c16 + 16 * jj;
      const int j = j0 + jl;
      const int dh = sm.d8[r][j], de = sm.e8[r][j];
      sm.Sbuf[r][j] =
          (acc[jj] + sm.rowhop[r][dh] + sm.KHs[jl][dh] + sm.rowedge[r][de]) * SCALE;
    }
    __syncthreads();
  }

  // row softmax over 512 entries; 16 lanes per row
  float m = -1e30f;
#pragma unroll 8
  for (int qq = 0; qq < 32; qq++) m = fmaxf(m, sm.Sbuf[r][c16 + 16 * qq]);
#pragma unroll
  for (int off = 8; off > 0; off >>= 1)
    m = fmaxf(m, __shfl_xor_sync(0xffffffffu, m, off));
  float l = 0.f;
#pragma unroll 8
  for (int qq = 0; qq < 32; qq++) {
    const int j = c16 + 16 * qq;
    const float p = __expf(sm.Sbuf[r][j] - m);
    sm.Sbuf[r][j] = p;
    l += p;
  }
#pragma unroll
  for (int off = 8; off > 0; off >>= 1) l += __shfl_xor_sync(0xffffffffu, l, off);
  const float inv = 1.f / l;
  if (c16 == 0) sm.rowinv[r] = inv;

  const size_t arow = ((size_t)bh * S + i0 + r) * S;
#pragma unroll 8
  for (int qq = 0; qq < 32; qq++) {
    const int j = c16 + 16 * qq;
    const float p = sm.Sbuf[r][j];
    g_Attn[arow + j] = p * inv;
    atomicAdd(&sm.binsH[r][sm.d8[r][j]], p);
    atomicAdd(&sm.binsE[r][sm.e8[r][j]], p);
  }
  __syncthreads();

  for (int idx = tid; idx < 16 * TH; idx += 256) {
    const int rr = idx >> 5, t = idx & 31;
    g_BinsH[(bh * S + i0 + rr) * TH + t] = sm.binsH[rr][t] * sm.rowinv[rr];
  }
  for (int idx = tid; idx < 16 * TE; idx += 256) {
    const int rr = idx >> 4, t = idx & 15;
    g_BinsE[(bh * S + i0 + rr) * TE + t] = sm.binsE[rr][t] * sm.rowinv[rr];
  }
}

// ---------------- AV: out = attn@Vh + binsH@vhe + binsE@vee -------------------
__global__ __launch_bounds__(256) void av_kernel(
    const float* __restrict__ vhe, const float* __restrict__ vee) {
  __shared__ float As[64][65];
  __shared__ float Vs[64][65];
  const int bh = blockIdx.x, h = bh % NH;
  const int i0 = blockIdx.y * 64;
  const int tid = threadIdx.x;
  const int tx = tid & 15, ty = tid >> 4;
  float acc[4][4] = {};

  for (int j0 = 0; j0 < S; j0 += 64) {
    for (int idx = tid; idx < 64 * 64; idx += 256) {
      const int rr = idx >> 6, c = idx & 63;
      As[rr][c] = g_Attn[((size_t)bh * S + i0 + rr) * S + j0 + c];
      Vs[rr][c] = g_Vh[(bh * S + j0 + rr) * DK + c];
    }
    __syncthreads();
#pragma unroll 8
    for (int kk = 0; kk < 64; kk++) {
      float a[4], vv[4];
#pragma unroll
      for (int ii = 0; ii < 4; ii++) a[ii] = As[ty * 4 + ii][kk];
#pragma unroll
      for (int jj = 0; jj < 4; jj++) vv[jj] = Vs[kk][tx * 4 + jj];
#pragma unroll
      for (int ii = 0; ii < 4; ii++)
#pragma unroll
        for (int jj = 0; jj < 4; jj++) acc[ii][jj] += a[ii] * vv[jj];
    }
    __syncthreads();
  }

  // hop bins
  for (int idx = tid; idx < 64 * TH; idx += 256)
    As[idx >> 5][idx & 31] = g_BinsH[(bh * S + i0 + (idx >> 5)) * TH + (idx & 31)];
  for (int idx = tid; idx < TH * DK; idx += 256)
    Vs[idx >> 6][idx & 63] = vhe[(idx >> 6) * HID + h * DK + (idx & 63)];
  __syncthreads();
#pragma unroll 8
  for (int kk = 0; kk < TH; kk++) {
    float a[4], vv[4];
#pragma unroll
    for (int ii = 0; ii < 4; ii++) a[ii] = As[ty * 4 + ii][kk];
#pragma unroll
    for (int jj = 0; jj < 4; jj++) vv[jj] = Vs[kk][tx * 4 + jj];
#pragma unroll
    for (int ii = 0; ii < 4; ii++)
#pragma unroll
      for (int jj = 0; jj < 4; jj++) acc[ii][jj] += a[ii] * vv[jj];
  }
  __syncthreads();

  // edge bins
  for (int idx = tid; idx < 64 * TE; idx += 256)
    As[idx >> 4][idx & 15] = g_BinsE[(bh * S + i0 + (idx >> 4)) * TE + (idx & 15)];
  for (int idx = tid; idx < TE * DK; idx += 256)
    Vs[idx >> 6][idx & 63] = vee[(idx >> 6) * HID + h * DK + (idx & 63)];
  __syncthreads();
#pragma unroll
  for (int kk = 0; kk < TE; kk++) {
    float a[4], vv[4];
#pragma unroll
    for (int ii = 0; ii < 4; ii++) a[ii] = As[ty * 4 + ii][kk];
#pragma unroll
    for (int jj = 0; jj < 4; jj++) vv[jj] = Vs[kk][tx * 4 + jj];
#pragma unroll
    for (int ii = 0; ii < 4; ii++)
#pragma unroll
      for (int jj = 0; jj < 4; jj++) acc[ii][jj] += a[ii] * vv[jj];
  }

#pragma unroll
  for (int ii = 0; ii < 4; ii++)
#pragma unroll
    for (int jj = 0; jj < 4; jj++)
      g_OutH[(bh * S + i0 + ty * 4 + ii) * DK + tx * 4 + jj] = acc[ii][jj];
}

// ---------------- launcher ----------------------------------------------------
extern "C" void kernel_launch(void* const* d_in, const int* in_sizes, int n_in,
                              void* d_out, int out_size) {
  (void)in_sizes; (void)n_in; (void)out_size;
  const float* q   = (const float*)d_in[0];
  const float* k   = (const float*)d_in[1];
  const float* v   = (const float*)d_in[2];
  const float* qhe = (const float*)d_in[3];
  const float* qee = (const float*)d_in[4];
  const float* khe = (const float*)d_in[5];
  const float* kee = (const float*)d_in[6];
  const float* vhe = (const float*)d_in[7];
  const float* vee = (const float*)d_in[8];
  const int* dist  = (const int*)d_in[9];
  const int* edge  = (const int*)d_in[10];
  const float* Wq = (const float*)d_in[11], *bq = (const float*)d_in[12];
  const float* Wk = (const float*)d_in[13], *bk = (const float*)d_in[14];
  const float* Wv = (const float*)d_in[15], *bv = (const float*)d_in[16];
  const float* Wo = (const float*)d_in[17], *bo = (const float*)d_in[18];
  float* out = (float*)d_out;

  cudaFuncSetAttribute(attn_kernel, cudaFuncAttributeMaxDynamicSharedMemorySize,
                       (int)sizeof(AttnSmem));

  const dim3 gg(8, 128);
  gemm512_kernel<0><<<gg, 256>>>(q, Wq, bq, nullptr);
  gemm512_kernel<1><<<gg, 256>>>(k, Wk, bk, nullptr);
  gemm512_kernel<2><<<gg, 256>>>(v, Wv, bv, nullptr);
  tables_kernel<<<dim3(BH, 16), 256>>>(qhe, qee, khe, kee);
  attn_kernel<<<dim3(BH, 32), 256, sizeof(AttnSmem)>>>(dist, edge);
  av_kernel<<<dim3(BH, 8), 256>>>(vhe, vee);
  gemm512_kernel<3><<<gg, 256>>>(nullptr, Wo, bo, out);
}

// round 2
// speedup vs baseline: 1.4937x; 1.4937x over previous
#include <cuda_runtime.h>

namespace {
constexpr int B = 16, S = 512, HID = 512, NH = 8, DK = 64, TH = 32, TE = 16;
constexpr int BH = B * NH;            // 128
constexpr float SCALE = 0.125f;       // dk^-0.5, dk=64
}

// ---------------- scratch (device globals; no runtime allocation) -------------
__device__ float g_Qh[BH * S * DK];
__device__ float g_Kh[BH * S * DK];
__device__ float g_Vh[BH * S * DK];
__device__ float g_QHop[BH * S * TH];
__device__ float g_KHop[BH * S * TH];
__device__ float g_EB[BH * S * TE];                 // QEdge + KEdge (row-indexed)
__device__ float g_Attn[(size_t)BH * S * S];        // 134 MB
__device__ float g_BinsH[BH * S * TH];
__device__ float g_BinsE[BH * S * TE];
__device__ float g_OutH[BH * S * DK];

// ---------------- tf32 helpers ------------------------------------------------
__device__ __forceinline__ float to_tf32(float x) {
  asm("cvt.rna.tf32.f32 %0, %0;" : "+f"(x));
  return x;
}

// D += A(16x8,row) * B(8x8,col);  frags: a[4], b[2], c[4]
__device__ __forceinline__ void mma_tf32(float* c, const float* a, const float* b) {
  const unsigned* A = reinterpret_cast<const unsigned*>(a);
  const unsigned* Bp = reinterpret_cast<const unsigned*>(b);
  asm volatile(
      "mma.sync.aligned.m16n8k8.row.col.f32.tf32.tf32.f32 "
      "{%0,%1,%2,%3}, {%4,%5,%6,%7}, {%8,%9}, {%0,%1,%2,%3};\n"
      : "+f"(c[0]), "+f"(c[1]), "+f"(c[2]), "+f"(c[3])
      : "r"(A[0]), "r"(A[1]), "r"(A[2]), "r"(A[3]), "r"(Bp[0]), "r"(Bp[1]));
}

// ---------------- proj GEMM: C = A @ W^T + bias (M=8192, N=512, K=512) --------
// TGT 0/1/2: A row-major; write head layout. TGT 3: A = g_OutH head layout; row-major out.
template <int TGT>
__global__ __launch_bounds__(256) void proj_mma(
    const float* __restrict__ A, const float* __restrict__ W,
    const float* __restrict__ bias, float* __restrict__ Cout) {
  __shared__ float As[128][36];
  __shared__ float Ws[64][36];
  const int m0 = blockIdx.y * 128, n0 = blockIdx.x * 64;
  const int tid = threadIdx.x;
  const int lane = tid & 31, wid = tid >> 5;
  const int wm = wid & 3, wn = wid >> 2;   // warp tile: 32 rows x 32 cols
  const int g = lane >> 2, t4 = lane & 3;
  float c[2][4][4] = {};

  for (int k0 = 0; k0 < 512; k0 += 32) {
    {  // A: 128x32, 2 threads/row
      const int r = tid >> 1, cb = (tid & 1) * 16;
#pragma unroll
      for (int i = 0; i < 4; i++) {
        const int cc = cb + i * 4;
        float4 v;
        if (TGT < 3) {
          v = *reinterpret_cast<const float4*>(&A[(m0 + r) * 512 + k0 + cc]);
        } else {
          const int n = m0 + r, kk = k0 + cc;
          const int bb = n >> 9, ii = n & 511, h = kk >> 6, d = kk & 63;
          v = *reinterpret_cast<const float4*>(&g_OutH[(((bb * NH + h) * S) + ii) * DK + d]);
        }
        As[r][cc + 0] = to_tf32(v.x); As[r][cc + 1] = to_tf32(v.y);
        As[r][cc + 2] = to_tf32(v.z); As[r][cc + 3] = to_tf32(v.w);
      }
    }
    {  // W: 64x32, 4 threads/row
      const int r = tid >> 2, cb = (tid & 3) * 8;
#pragma unroll
      for (int i = 0; i < 2; i++) {
        const int cc = cb + i * 4;
        float4 v = *reinterpret_cast<const float4*>(&W[(n0 + r) * 512 + k0 + cc]);
        Ws[r][cc + 0] = to_tf32(v.x); Ws[r][cc + 1] = to_tf32(v.y);
        Ws[r][cc + 2] = to_tf32(v.z); Ws[r][cc + 3] = to_tf32(v.w);
      }
    }
    __syncthreads();
#pragma unroll
    for (int k8 = 0; k8 < 4; k8++) {
      const int kk = k8 * 8;
      float a[2][4], b[4][2];
#pragma unroll
      for (int mi = 0; mi < 2; mi++) {
        const int rr = wm * 32 + mi * 16 + g;
        a[mi][0] = As[rr][kk + t4];     a[mi][1] = As[rr + 8][kk + t4];
        a[mi][2] = As[rr][kk + t4 + 4]; a[mi][3] = As[rr + 8][kk + t4 + 4];
      }
#pragma unroll
      for (int ni = 0; ni < 4; ni++) {
        const int cc = wn * 32 + ni * 8 + g;
        b[ni][0] = Ws[cc][kk + t4]; b[ni][1] = Ws[cc][kk + t4 + 4];
      }
#pragma unroll
      for (int mi = 0; mi < 2; mi++)
#pragma unroll
        for (int ni = 0; ni < 4; ni++) mma_tf32(c[mi][ni], a[mi], b[ni]);
    }
    __syncthreads();
  }
#pragma unroll
  for (int mi = 0; mi < 2; mi++)
#pragma unroll
    for (int ni = 0; ni < 4; ni++)
#pragma unroll
      for (int fi = 0; fi < 4; fi++) {
        const int row = m0 + wm * 32 + mi * 16 + g + ((fi >= 2) ? 8 : 0);
        const int col = n0 + wn * 32 + ni * 8 + t4 * 2 + (fi & 1);
        const float v = c[mi][ni][fi] + bias[col];
        if (TGT == 3) {
          Cout[row * 512 + col] = v;
        } else {
          const int bb = row >> 9, ii = row & 511, h = col >> 6, d = col & 63;
          float* dst = (TGT == 0) ? g_Qh : (TGT == 1) ? g_Kh : g_Vh;
          dst[(((bb * NH + h) * S) + ii) * DK + d] = v;
        }
      }
}

// ---------------- tables: QHop/KHop/EB via mma --------------------------------
// Per block: 64 rows. QT = Q[64x64] @ Ecat_q^T[48x64]; KT likewise; split outputs.
__global__ __launch_bounds__(256) void tables_mma(
    const float* __restrict__ qhe, const float* __restrict__ qee,
    const float* __restrict__ khe, const float* __restrict__ kee) {
  extern __shared__ float tsm[];
  float (*Qs)[68]  = reinterpret_cast<float(*)[68]>(tsm);
  float (*Ks2)[68] = reinterpret_cast<float(*)[68]>(tsm + 64 * 68);
  float (*Eq)[68]  = reinterpret_cast<float(*)[68]>(tsm + 128 * 68);
  float (*Ek)[68]  = reinterpret_cast<float(*)[68]>(tsm + 176 * 68);
  const int bh = blockIdx.x, h = bh & 7;
  const int i0 = blockIdx.y * 64;
  const int tid = threadIdx.x;
  const int lane = tid & 31, wid = tid >> 5;
  const int wm = wid & 3, wn = wid >> 2;  // warp: 16 rows x 24 cols
  const int g = lane >> 2, t4 = lane & 3;

  for (int i = tid; i < 64 * 16; i += 256) {
    const int r = i >> 4, cc = (i & 15) * 4;
    float4 q = *reinterpret_cast<const float4*>(&g_Qh[(bh * S + i0 + r) * DK + cc]);
    float4 k = *reinterpret_cast<const float4*>(&g_Kh[(bh * S + i0 + r) * DK + cc]);
    Qs[r][cc] = to_tf32(q.x); Qs[r][cc + 1] = to_tf32(q.y);
    Qs[r][cc + 2] = to_tf32(q.z); Qs[r][cc + 3] = to_tf32(q.w);
    Ks2[r][cc] = to_tf32(k.x); Ks2[r][cc + 1] = to_tf32(k.y);
    Ks2[r][cc + 2] = to_tf32(k.z); Ks2[r][cc + 3] = to_tf32(k.w);
  }
  for (int i = tid; i < 48 * 16; i += 256) {
    const int r = i >> 4, cc = (i & 15) * 4;
    const float* sq = (r < TH) ? &qhe[r * HID + h * DK + cc] : &qee[(r - TH) * HID + h * DK + cc];
    const float* sk = (r < TH) ? &khe[r * HID + h * DK + cc] : &kee[(r - TH) * HID + h * DK + cc];
    float4 vq = *reinterpret_cast<const float4*>(sq);
    float4 vk = *reinterpret_cast<const float4*>(sk);
    Eq[r][cc] = to_tf32(vq.x); Eq[r][cc + 1] = to_tf32(vq.y);
    Eq[r][cc + 2] = to_tf32(vq.z); Eq[r][cc + 3] = to_tf32(vq.w);
    Ek[r][cc] = to_tf32(vk.x); Ek[r][cc + 1] = to_tf32(vk.y);
    Ek[r][cc + 2] = to_tf32(vk.z); Ek[r][cc + 3] = to_tf32(vk.w);
  }
  __syncthreads();

  float cQ[3][4] = {}, cK[3][4] = {};
#pragma unroll
  for (int k8 = 0; k8 < 8; k8++) {
    const int kk = k8 * 8;
    const int rr = wm * 16 + g;
    float aQ[4], aK[4], bQ[3][2], bK[3][2];
    aQ[0] = Qs[rr][kk + t4];      aQ[1] = Qs[rr + 8][kk + t4];
    aQ[2] = Qs[rr][kk + t4 + 4];  aQ[3] = Qs[rr + 8][kk + t4 + 4];
    aK[0] = Ks2[rr][kk + t4];     aK[1] = Ks2[rr + 8][kk + t4];
    aK[2] = Ks2[rr][kk + t4 + 4]; aK[3] = Ks2[rr + 8][kk + t4 + 4];
#pragma unroll
    for (int ni = 0; ni < 3; ni++) {
      const int cc = wn * 24 + ni * 8 + g;
      bQ[ni][0] = Eq[cc][kk + t4]; bQ[ni][1] = Eq[cc][kk + t4 + 4];
      bK[ni][0] = Ek[cc][kk + t4]; bK[ni][1] = Ek[cc][kk + t4 + 4];
    }
#pragma unroll
    for (int ni = 0; ni < 3; ni++) {
      mma_tf32(cQ[ni], aQ, bQ[ni]);
      mma_tf32(cK[ni], aK, bK[ni]);
    }
  }
#pragma unroll
  for (int ni = 0; ni < 3; ni++)
#pragma unroll
    for (int fi = 0; fi < 4; fi++) {
      const int row = i0 + wm * 16 + g + ((fi >= 2) ? 8 : 0);
      const int col = wn * 24 + ni * 8 + t4 * 2 + (fi & 1);
      if (col < TH) {
        g_QHop[(bh * S + row) * TH + col] = cQ[ni][fi];
        g_KHop[(bh * S + row) * TH + col] = cK[ni][fi];
      } else {
        g_EB[(bh * S + row) * TE + (col - TH)] = cQ[ni][fi] + cK[ni][fi];
      }
    }
}

// ---------------- fused scores + bias + softmax + bins ------------------------
struct AttnSmem {
  float Sbuf[32][512];       // 64KB
  float Ks[128][68];
  float KHs[128][36];
  float Qs[32][68];
  float rowhop[32][TH];
  float rowedge[32][TE];
  float binsH[32][TH];
  float binsE[32][TE];
  float rowinv[32];
  unsigned char d8[32][512];
  unsigned char e8[32][512];
};

__global__ __launch_bounds__(256) void attn_kernel(
    const int* __restrict__ dist, const int* __restrict__ edge) {
  extern __shared__ char smem_raw[];
  AttnSmem& sm = *reinterpret_cast<AttnSmem*>(smem_raw);
  const int bh = blockIdx.x, b = bh >> 3;
  const int i0 = blockIdx.y * 32;
  const int tid = threadIdx.x;
  const int lane = tid & 31, wid = tid >> 5;
  const int g = lane >> 2, t4 = lane & 3;

  // loads
  for (int i = tid; i < 32 * 16; i += 256) {
    const int r = i >> 4, cc = (i & 15) * 4;
    float4 q = *reinterpret_cast<const float4*>(&g_Qh[(bh * S + i0 + r) * DK + cc]);
    sm.Qs[r][cc] = to_tf32(q.x); sm.Qs[r][cc + 1] = to_tf32(q.y);
    sm.Qs[r][cc + 2] = to_tf32(q.z); sm.Qs[r][cc + 3] = to_tf32(q.w);
  }
  for (int i = tid; i < 32 * TH; i += 256) {
    sm.rowhop[i >> 5][i & 31] = g_QHop[(bh * S + i0 + (i >> 5)) * TH + (i & 31)];
    sm.binsH[i >> 5][i & 31] = 0.f;
  }
  for (int i = tid; i < 32 * TE; i += 256) {
    sm.rowedge[i >> 4][i & 15] = g_EB[(bh * S + i0 + (i >> 4)) * TE + (i & 15)];
    sm.binsE[i >> 4][i & 15] = 0.f;
  }
  for (int i = tid; i < 32 * 128; i += 256) {  // 4 elems at a time
    const int r = i >> 7, c4 = (i & 127) * 4;
    const size_t base = ((size_t)b * S + i0 + r) * S + c4;
    int4 dv = *reinterpret_cast<const int4*>(&dist[base]);
    int4 ev = *reinterpret_cast<const int4*>(&edge[base]);
    *reinterpret_cast<uchar4*>(&sm.d8[r][c4]) =
        make_uchar4((unsigned char)dv.x, (unsigned char)dv.y, (unsigned char)dv.z, (unsigned char)dv.w);
    *reinterpret_cast<uchar4*>(&sm.e8[r][c4]) =
        make_uchar4((unsigned char)ev.x, (unsigned char)ev.y, (unsigned char)ev.z, (unsigned char)ev.w);
  }
  __syncthreads();

  // phase 1: QK + bias, 4 sweeps of 128 keys
  for (int s = 0; s < 4; s++) {
    const int j0 = s * 128;
    for (int i = tid; i < 128 * 16; i += 256) {
      const int r = i >> 4, cc = (i & 15) * 4;
      float4 k = *reinterpret_cast<const float4*>(&g_Kh[(bh * S + j0 + r) * DK + cc]);
      sm.Ks[r][cc] = to_tf32(k.x); sm.Ks[r][cc + 1] = to_tf32(k.y);
      sm.Ks[r][cc + 2] = to_tf32(k.z); sm.Ks[r][cc + 3] = to_tf32(k.w);
    }
    for (int i = tid; i < 128 * 8; i += 256) {
      const int r = i >> 3, cc = (i & 7) * 4;
      float4 v = *reinterpret_cast<const float4*>(&g_KHop[(bh * S + j0 + r) * TH + cc]);
      sm.KHs[r][cc] = v.x; sm.KHs[r][cc + 1] = v.y;
      sm.KHs[r][cc + 2] = v.z; sm.KHs[r][cc + 3] = v.w;
    }
    __syncthreads();

    float c[2][2][4] = {};
#pragma unroll
    for (int k8 = 0; k8 < 8; k8++) {
      const int kk = k8 * 8;
      float a[2][4], bf[2][2];
#pragma unroll
      for (int mi = 0; mi < 2; mi++) {
        const int rr = mi * 16 + g;
        a[mi][0] = sm.Qs[rr][kk + t4];     a[mi][1] = sm.Qs[rr + 8][kk + t4];
        a[mi][2] = sm.Qs[rr][kk + t4 + 4]; a[mi][3] = sm.Qs[rr + 8][kk + t4 + 4];
      }
#pragma unroll
      for (int ni = 0; ni < 2; ni++) {
        const int jl = wid * 16 + ni * 8 + g;
        bf[ni][0] = sm.Ks[jl][kk + t4]; bf[ni][1] = sm.Ks[jl][kk + t4 + 4];
      }
#pragma unroll
      for (int mi = 0; mi < 2; mi++)
#pragma unroll
        for (int ni = 0; ni < 2; ni++) mma_tf32(c[mi][ni], a[mi], bf[ni]);
    }
#pragma unroll
    for (int mi = 0; mi < 2; mi++)
#pragma unroll
      for (int ni = 0; ni < 2; ni++)
#pragma unroll
        for (int fi = 0; fi < 4; fi++) {
          const int row = mi * 16 + g + ((fi >= 2) ? 8 : 0);
          const int jl = wid * 16 + ni * 8 + t4 * 2 + (fi & 1);
          const int jg = j0 + jl;
          const int dh = sm.d8[row][jg], de = sm.e8[row][jg];
          sm.Sbuf[row][jg] =
              (c[mi][ni][fi] + sm.rowhop[row][dh] + sm.KHs[jl][dh] + sm.rowedge[row][de]) * SCALE;
        }
    __syncthreads();
  }

  // phase 2: softmax (8 lanes/row) + bins + write normalized attn
  const int r = tid >> 3, l8 = tid & 7;
  float m = -1e30f;
#pragma unroll 16
  for (int q = 0; q < 64; q++) m = fmaxf(m, sm.Sbuf[r][l8 + 8 * q]);
#pragma unroll
  for (int off = 4; off > 0; off >>= 1) m = fmaxf(m, __shfl_xor_sync(0xffffffffu, m, off));
  float l = 0.f;
#pragma unroll 16
  for (int q = 0; q < 64; q++) {
    const int j = l8 + 8 * q;
    const float p = __expf(sm.Sbuf[r][j] - m);
    sm.Sbuf[r][j] = p;
    l += p;
  }
#pragma unroll
  for (int off = 4; off > 0; off >>= 1) l += __shfl_xor_sync(0xffffffffu, l, off);
  const float inv = 1.f / l;
  if (l8 == 0) sm.rowinv[r] = inv;

  const size_t arow = ((size_t)bh * S + i0 + r) * S;
#pragma unroll 16
  for (int q = 0; q < 64; q++) {
    const int j = l8 + 8 * q;
    const float p = sm.Sbuf[r][j];
    g_Attn[arow + j] = p * inv;
    atomicAdd(&sm.binsH[r][sm.d8[r][j]], p);
    atomicAdd(&sm.binsE[r][sm.e8[r][j]], p);
  }
  __syncthreads();

  for (int i = tid; i < 32 * TH; i += 256)
    g_BinsH[(bh * S + i0 + (i >> 5)) * TH + (i & 31)] = sm.binsH[i >> 5][i & 31] * sm.rowinv[i >> 5];
  for (int i = tid; i < 32 * TE; i += 256)
    g_BinsE[(bh * S + i0 + (i >> 4)) * TE + (i & 15)] = sm.binsE[i >> 4][i & 15] * sm.rowinv[i >> 4];
}

// ---------------- AV: out = attn@Vh + binsH@vhe + binsE@vee (mma) -------------
__global__ __launch_bounds__(256) void av_mma(
    const float* __restrict__ vhe, const float* __restrict__ vee) {
  extern __shared__ float avsm[];
  float (*As)[132] = reinterpret_cast<float(*)[132]>(avsm);           // 64x128 chunk
  float (*Vs)[68]  = reinterpret_cast<float(*)[68]>(avsm + 64 * 132);
  const int bh = blockIdx.x, h = bh & 7;
  const int i0 = blockIdx.y * 64;
  const int tid = threadIdx.x;
  const int lane = tid & 31, wid = tid >> 5;
  const int wm = wid & 3, wn = wid >> 2;  // warp: 16 rows x 32 cols
  const int g = lane >> 2, t4 = lane & 3;
  float c[4][4] = {};

  for (int ch = 0; ch < 4; ch++) {
    const int j0 = ch * 128;
    for (int i = tid; i < 64 * 32; i += 256) {
      const int r = i >> 5, cc = (i & 31) * 4;
      float4 v = *reinterpret_cast<const float4*>(&g_Attn[((size_t)bh * S + i0 + r) * S + j0 + cc]);
      As[r][cc] = to_tf32(v.x); As[r][cc + 1] = to_tf32(v.y);
      As[r][cc + 2] = to_tf32(v.z); As[r][cc + 3] = to_tf32(v.w);
    }
    for (int i = tid; i < 128 * 16; i += 256) {
      const int r = i >> 4, cc = (i & 15) * 4;
      float4 v = *reinterpret_cast<const float4*>(&g_Vh[(bh * S + j0 + r) * DK + cc]);
      Vs[r][cc] = to_tf32(v.x); Vs[r][cc + 1] = to_tf32(v.y);
      Vs[r][cc + 2] = to_tf32(v.z); Vs[r][cc + 3] = to_tf32(v.w);
    }
    __syncthreads();
#pragma unroll
    for (int ks = 0; ks < 16; ks++) {
      const int kk = ks * 8;
      const int rr = wm * 16 + g;
      float a[4], bf[4][2];
      a[0] = As[rr][kk + t4];     a[1] = As[rr + 8][kk + t4];
      a[2] = As[rr][kk + t4 + 4]; a[3] = As[rr + 8][kk + t4 + 4];
#pragma unroll
      for (int ni = 0; ni < 4; ni++) {
        const int cc = wn * 32 + ni * 8 + g;
        bf[ni][0] = Vs[kk + t4][cc]; bf[ni][1] = Vs[kk + t4 + 4][cc];
      }
#pragma unroll
      for (int ni = 0; ni < 4; ni++) mma_tf32(c[ni], a, bf[ni]);
    }
    __syncthreads();
  }

  // bins terms
  float (*Bh)[36]   = reinterpret_cast<float(*)[36]>(avsm);           // 64x32
  float (*Vhe)[68]  = reinterpret_cast<float(*)[68]>(avsm + 4096);    // 32x64
  float (*Be)[20]   = reinterpret_cast<float(*)[20]>(avsm + 8192);    // 64x16
  float (*Vee)[68]  = reinterpret_cast<float(*)[68]>(avsm + 10240);   // 16x64
  for (int i = tid; i < 64 * 8; i += 256) {
    const int r = i >> 3, cc = (i & 7) * 4;
    float4 v = *reinterpret_cast<const float4*>(&g_BinsH[(bh * S + i0 + r) * TH + cc]);
    Bh[r][cc] = to_tf32(v.x); Bh[r][cc + 1] = to_tf32(v.y);
    Bh[r][cc + 2] = to_tf32(v.z); Bh[r][cc + 3] = to_tf32(v.w);
  }
  for (int i = tid; i < 32 * 16; i += 256) {
    const int r = i >> 4, cc = (i & 15) * 4;
    float4 v = *reinterpret_cast<const float4*>(&vhe[r * HID + h * DK + cc]);
    Vhe[r][cc] = to_tf32(v.x); Vhe[r][cc + 1] = to_tf32(v.y);
    Vhe[r][cc + 2] = to_tf32(v.z); Vhe[r][cc + 3] = to_tf32(v.w);
  }
  for (int i = tid; i < 64 * 4; i += 256) {
    const int r = i >> 2, cc = (i & 3) * 4;
    float4 v = *reinterpret_cast<const float4*>(&g_BinsE[(bh * S + i0 + r) * TE + cc]);
    Be[r][cc] = to_tf32(v.x); Be[r][cc + 1] = to_tf32(v.y);
    Be[r][cc + 2] = to_tf32(v.z); Be[r][cc + 3] = to_tf32(v.w);
  }
  for (int i = tid; i < 16 * 16; i += 256) {
    const int r = i >> 4, cc = (i & 15) * 4;
    float4 v = *reinterpret_cast<const float4*>(&vee[r * HID + h * DK + cc]);
    Vee[r][cc] = to_tf32(v.x); Vee[r][cc + 1] = to_tf32(v.y);
    Vee[r][cc + 2] = to_tf32(v.z); Vee[r][cc + 3] = to_tf32(v.w);
  }
  __syncthreads();
#pragma unroll
  for (int ks = 0; ks < 4; ks++) {  // hop, K=32
    const int kk = ks * 8;
    const int rr = wm * 16 + g;
    float a[4], bf[4][2];
    a[0] = Bh[rr][kk + t4];     a[1] = Bh[rr + 8][kk + t4];
    a[2] = Bh[rr][kk + t4 + 4]; a[3] = Bh[rr + 8][kk + t4 + 4];
#pragma unroll
    for (int ni = 0; ni < 4; ni++) {
      const int cc = wn * 32 + ni * 8 + g;
      bf[ni][0] = Vhe[kk + t4][cc]; bf[ni][1] = Vhe[kk + t4 + 4][cc];
    }
#pragma unroll
    for (int ni = 0; ni < 4; ni++) mma_tf32(c[ni], a, bf[ni]);
  }
#pragma unroll
  for (int ks = 0; ks < 2; ks++) {  // edge, K=16
    const int kk = ks * 8;
    const int rr = wm * 16 + g;
    float a[4], bf[4][2];
    a[0] = Be[rr][kk + t4];     a[1] = Be[rr + 8][kk + t4];
    a[2] = Be[rr][kk + t4 + 4]; a[3] = Be[rr + 8][kk + t4 + 4];
#pragma unroll
    for (int ni = 0; ni < 4; ni++) {
      const int cc = wn * 32 + ni * 8 + g;
      bf[ni][0] = Vee[kk + t4][cc]; bf[ni][1] = Vee[kk + t4 + 4][cc];
    }
#pragma unroll
    for (int ni = 0; ni < 4; ni++) mma_tf32(c[ni], a, bf[ni]);
  }

#pragma unroll
  for (int ni = 0; ni < 4; ni++)
#pragma unroll
    for (int fi = 0; fi < 4; fi++) {
      const int row = i0 + wm * 16 + g + ((fi >= 2) ? 8 : 0);
      const int col = wn * 32 + ni * 8 + t4 * 2 + (fi & 1);
      g_OutH[(bh * S + row) * DK + col] = c[ni][fi];
    }
}

// ---------------- launcher ----------------------------------------------------
extern "C" void kernel_launch(void* const* d_in, const int* in_sizes, int n_in,
                              void* d_out, int out_size) {
  (void)in_sizes; (void)n_in; (void)out_size;
  const float* q   = (const float*)d_in[0];
  const float* k   = (const float*)d_in[1];
  const float* v   = (const float*)d_in[2];
  const float* qhe = (const float*)d_in[3];
  const float* qee = (const float*)d_in[4];
  const float* khe = (const float*)d_in[5];
  const float* kee = (const float*)d_in[6];
  const float* vhe = (const float*)d_in[7];
  const float* vee = (const float*)d_in[8];
  const int* dist  = (const int*)d_in[9];
  const int* edge  = (const int*)d_in[10];
  const float* Wq = (const float*)d_in[11], *bq = (const float*)d_in[12];
  const float* Wk = (const float*)d_in[13], *bk = (const float*)d_in[14];
  const float* Wv = (const float*)d_in[15], *bv = (const float*)d_in[16];
  const float* Wo = (const float*)d_in[17], *bo = (const float*)d_in[18];
  float* out = (float*)d_out;

  const int tables_smem = 224 * 68 * 4;
  const int attn_smem = (int)sizeof(AttnSmem);
  const int av_smem = (64 * 132 + 128 * 68) * 4;
  cudaFuncSetAttribute(tables_mma, cudaFuncAttributeMaxDynamicSharedMemorySize, tables_smem);
  cudaFuncSetAttribute(attn_kernel, cudaFuncAttributeMaxDynamicSharedMemorySize, attn_smem);
  cudaFuncSetAttribute(av_mma, cudaFuncAttributeMaxDynamicSharedMemorySize, av_smem);

  const dim3 gp(8, 64);  // N/64, M/128
  proj_mma<0><<<gp, 256>>>(q, Wq, bq, nullptr);
  proj_mma<1><<<gp, 256>>>(k, Wk, bk, nullptr);
  proj_mma<2><<<gp, 256>>>(v, Wv, bv, nullptr);
  tables_mma<<<dim3(BH, 8), 256, tables_smem>>>(qhe, qee, khe, kee);
  attn_kernel<<<dim3(BH, 16), 256, attn_smem>>>(dist, edge);
  av_mma<<<dim3(BH, 8), 256, av_smem>>>(vhe, vee);
  proj_mma<3><<<gp, 256>>>(nullptr, Wo, bo, out);
}

// round 3
// speedup vs baseline: 2.4104x; 1.6137x over previous
#include <cuda_runtime.h>

namespace {
constexpr int B = 16, S = 512, HID = 512, NH = 8, DK = 64, TH = 32, TE = 16;
constexpr int BH = B * NH;            // 128
constexpr float SC2 = 0.125f * 1.44269504088896f;  // scale * log2(e)
}

// ---------------- scratch (device globals; no runtime allocation) -------------
__device__ float g_Qh[BH * S * DK];
__device__ float g_Kh[BH * S * DK];
__device__ float g_Vh[BH * S * DK];
__device__ float g_QHop[BH * S * TH];
__device__ float g_KHop[BH * S * TH];
__device__ float g_EB[BH * S * TE];                  // QEdge + KEdge (row-indexed)
__device__ float g_OutH[BH * S * DK];
__device__ unsigned short g_DE16[(size_t)B * S * S]; // packed dist|edge<<8 (8.4MB)

// ---------------- tf32 helpers ------------------------------------------------
__device__ __forceinline__ float to_tf32(float x) {
  asm("cvt.rna.tf32.f32 %0, %0;" : "+f"(x));
  return x;
}
__device__ __forceinline__ float fast_exp2(float x) {
  asm("ex2.approx.f32 %0, %0;" : "+f"(x));
  return x;
}

// D += A(16x8,row) * B(8x8,col);  frags: a[4], b[2], c[4]
__device__ __forceinline__ void mma_tf32(float* c, const float* a, const float* b) {
  const unsigned* A = reinterpret_cast<const unsigned*>(a);
  const unsigned* Bp = reinterpret_cast<const unsigned*>(b);
  asm volatile(
      "mma.sync.aligned.m16n8k8.row.col.f32.tf32.tf32.f32 "
      "{%0,%1,%2,%3}, {%4,%5,%6,%7}, {%8,%9}, {%0,%1,%2,%3};\n"
      : "+f"(c[0]), "+f"(c[1]), "+f"(c[2]), "+f"(c[3])
      : "r"(A[0]), "r"(A[1]), "r"(A[2]), "r"(A[3]), "r"(Bp[0]), "r"(Bp[1]));
}

// ---------------- pack dist/edge into uint16 ---------------------------------
__global__ __launch_bounds__(256) void pack_kernel(const int* __restrict__ dist,
                                                   const int* __restrict__ edge) {
  const size_t i = (size_t)blockIdx.x * 256 + threadIdx.x;  // per 4 elements
  const size_t n4 = (size_t)B * S * S / 4;
  if (i >= n4) return;
  int4 d = reinterpret_cast<const int4*>(dist)[i];
  int4 e = reinterpret_cast<const int4*>(edge)[i];
  ushort4 o;
  o.x = (unsigned short)(d.x | (e.x << 8));
  o.y = (unsigned short)(d.y | (e.y << 8));
  o.z = (unsigned short)(d.z | (e.z << 8));
  o.w = (unsigned short)(d.w | (e.w << 8));
  reinterpret_cast<ushort4*>(g_DE16)[i] = o;
}

// ---------------- proj GEMM: C = A @ W^T + bias (M=8192, N=512, K=512) --------
template <int TGT>
__global__ __launch_bounds__(256) void proj_mma(
    const float* __restrict__ A, const float* __restrict__ W,
    const float* __restrict__ bias, float* __restrict__ Cout) {
  __shared__ float As[128][36];
  __shared__ float Ws[64][36];
  const int m0 = blockIdx.y * 128, n0 = blockIdx.x * 64;
  const int tid = threadIdx.x;
  const int lane = tid & 31, wid = tid >> 5;
  const int wm = wid & 3, wn = wid >> 2;   // warp tile: 32 rows x 32 cols
  const int g = lane >> 2, t4 = lane & 3;
  float c[2][4][4] = {};

  for (int k0 = 0; k0 < 512; k0 += 32) {
    {  // A: 128x32, 2 threads/row
      const int r = tid >> 1, cb = (tid & 1) * 16;
#pragma unroll
      for (int i = 0; i < 4; i++) {
        const int cc = cb + i * 4;
        float4 v;
        if (TGT < 3) {
          v = *reinterpret_cast<const float4*>(&A[(m0 + r) * 512 + k0 + cc]);
        } else {
          const int n = m0 + r, kk = k0 + cc;
          const int bb = n >> 9, ii = n & 511, h = kk >> 6, d = kk & 63;
          v = *reinterpret_cast<const float4*>(&g_OutH[(((bb * NH + h) * S) + ii) * DK + d]);
        }
        As[r][cc + 0] = to_tf32(v.x); As[r][cc + 1] = to_tf32(v.y);
        As[r][cc + 2] = to_tf32(v.z); As[r][cc + 3] = to_tf32(v.w);
      }
    }
    {  // W: 64x32, 4 threads/row
      const int r = tid >> 2, cb = (tid & 3) * 8;
#pragma unroll
      for (int i = 0; i < 2; i++) {
        const int cc = cb + i * 4;
        float4 v = *reinterpret_cast<const float4*>(&W[(n0 + r) * 512 + k0 + cc]);
        Ws[r][cc + 0] = to_tf32(v.x); Ws[r][cc + 1] = to_tf32(v.y);
        Ws[r][cc + 2] = to_tf32(v.z); Ws[r][cc + 3] = to_tf32(v.w);
      }
    }
    __syncthreads();
#pragma unroll
    for (int k8 = 0; k8 < 4; k8++) {
      const int kk = k8 * 8;
      float a[2][4], b[4][2];
#pragma unroll
      for (int mi = 0; mi < 2; mi++) {
        const int rr = wm * 32 + mi * 16 + g;
        a[mi][0] = As[rr][kk + t4];     a[mi][1] = As[rr + 8][kk + t4];
        a[mi][2] = As[rr][kk + t4 + 4]; a[mi][3] = As[rr + 8][kk + t4 + 4];
      }
#pragma unroll
      for (int ni = 0; ni < 4; ni++) {
        const int cc = wn * 32 + ni * 8 + g;
        b[ni][0] = Ws[cc][kk + t4]; b[ni][1] = Ws[cc][kk + t4 + 4];
      }
#pragma unroll
      for (int mi = 0; mi < 2; mi++)
#pragma unroll
        for (int ni = 0; ni < 4; ni++) mma_tf32(c[mi][ni], a[mi], b[ni]);
    }
    __syncthreads();
  }
#pragma unroll
  for (int mi = 0; mi < 2; mi++)
#pragma unroll
    for (int ni = 0; ni < 4; ni++)
#pragma unroll
      for (int fi = 0; fi < 4; fi++) {
        const int row = m0 + wm * 32 + mi * 16 + g + ((fi >= 2) ? 8 : 0);
        const int col = n0 + wn * 32 + ni * 8 + t4 * 2 + (fi & 1);
        const float v = c[mi][ni][fi] + bias[col];
        if (TGT == 3) {
          Cout[row * 512 + col] = v;
        } else {
          const int bb = row >> 9, ii = row & 511, h = col >> 6, d = col & 63;
          float* dst = (TGT == 0) ? g_Qh : (TGT == 1) ? g_Kh : g_Vh;
          dst[(((bb * NH + h) * S) + ii) * DK + d] = v;
        }
      }
}

// ---------------- tables: QHop/KHop/EB via mma --------------------------------
__global__ __launch_bounds__(256) void tables_mma(
    const float* __restrict__ qhe, const float* __restrict__ qee,
    const float* __restrict__ khe, const float* __restrict__ kee) {
  extern __shared__ float tsm[];
  float (*Qs)[68]  = reinterpret_cast<float(*)[68]>(tsm);
  float (*Ks2)[68] = reinterpret_cast<float(*)[68]>(tsm + 64 * 68);
  float (*Eq)[68]  = reinterpret_cast<float(*)[68]>(tsm + 128 * 68);
  float (*Ek)[68]  = reinterpret_cast<float(*)[68]>(tsm + 176 * 68);
  const int bh = blockIdx.x, h = bh & 7;
  const int i0 = blockIdx.y * 64;
  const int tid = threadIdx.x;
  const int lane = tid & 31, wid = tid >> 5;
  const int wm = wid & 3, wn = wid >> 2;  // warp: 16 rows x 24 cols
  const int g = lane >> 2, t4 = lane & 3;

  for (int i = tid; i < 64 * 16; i += 256) {
    const int r = i >> 4, cc = (i & 15) * 4;
    float4 q = *reinterpret_cast<const float4*>(&g_Qh[(bh * S + i0 + r) * DK + cc]);
    float4 k = *reinterpret_cast<const float4*>(&g_Kh[(bh * S + i0 + r) * DK + cc]);
    Qs[r][cc] = to_tf32(q.x); Qs[r][cc + 1] = to_tf32(q.y);
    Qs[r][cc + 2] = to_tf32(q.z); Qs[r][cc + 3] = to_tf32(q.w);
    Ks2[r][cc] = to_tf32(k.x); Ks2[r][cc + 1] = to_tf32(k.y);
    Ks2[r][cc + 2] = to_tf32(k.z); Ks2[r][cc + 3] = to_tf32(k.w);
  }
  for (int i = tid; i < 48 * 16; i += 256) {
    const int r = i >> 4, cc = (i & 15) * 4;
    const float* sq = (r < TH) ? &qhe[r * HID + h * DK + cc] : &qee[(r - TH) * HID + h * DK + cc];
    const float* sk = (r < TH) ? &khe[r * HID + h * DK + cc] : &kee[(r - TH) * HID + h * DK + cc];
    float4 vq = *reinterpret_cast<const float4*>(sq);
    float4 vk = *reinterpret_cast<const float4*>(sk);
    Eq[r][cc] = to_tf32(vq.x); Eq[r][cc + 1] = to_tf32(vq.y);
    Eq[r][cc + 2] = to_tf32(vq.z); Eq[r][cc + 3] = to_tf32(vq.w);
    Ek[r][cc] = to_tf32(vk.x); Ek[r][cc + 1] = to_tf32(vk.y);
    Ek[r][cc + 2] = to_tf32(vk.z); Ek[r][cc + 3] = to_tf32(vk.w);
  }
  __syncthreads();

  float cQ[3][4] = {}, cK[3][4] = {};
#pragma unroll
  for (int k8 = 0; k8 < 8; k8++) {
    const int kk = k8 * 8;
    const int rr = wm * 16 + g;
    float aQ[4], aK[4], bQ[3][2], bK[3][2];
    aQ[0] = Qs[rr][kk + t4];      aQ[1] = Qs[rr + 8][kk + t4];
    aQ[2] = Qs[rr][kk + t4 + 4];  aQ[3] = Qs[rr + 8][kk + t4 + 4];
    aK[0] = Ks2[rr][kk + t4];     aK[1] = Ks2[rr + 8][kk + t4];
    aK[2] = Ks2[rr][kk + t4 + 4]; aK[3] = Ks2[rr + 8][kk + t4 + 4];
#pragma unroll
    for (int ni = 0; ni < 3; ni++) {
      const int cc = wn * 24 + ni * 8 + g;
      bQ[ni][0] = Eq[cc][kk + t4]; bQ[ni][1] = Eq[cc][kk + t4 + 4];
      bK[ni][0] = Ek[cc][kk + t4]; bK[ni][1] = Ek[cc][kk + t4 + 4];
    }
#pragma unroll
    for (int ni = 0; ni < 3; ni++) {
      mma_tf32(cQ[ni], aQ, bQ[ni]);
      mma_tf32(cK[ni], aK, bK[ni]);
    }
  }
#pragma unroll
  for (int ni = 0; ni < 3; ni++)
#pragma unroll
    for (int fi = 0; fi < 4; fi++) {
      const int row = i0 + wm * 16 + g + ((fi >= 2) ? 8 : 0);
      const int col = wn * 24 + ni * 8 + t4 * 2 + (fi & 1);
      if (col < TH) {
        g_QHop[(bh * S + row) * TH + col] = cQ[ni][fi];
        g_KHop[(bh * S + row) * TH + col] = cK[ni][fi];
      } else {
        g_EB[(bh * S + row) * TE + (col - TH)] = cQ[ni][fi] + cK[ni][fi];
      }
    }
}

// ---------------- fused flash attention + bins --------------------------------
struct FSmem {
  float Sc[64][132];          // scores / p chunk (also bins A in epilogue)
  float Ks[128][68];
  float Vs[128][68];          // also value-emb tables in epilogue
  float KHs[128][36];
  float Qs[64][68];
  float rowhop[64][32];
  float rowedge[64][16];
  float binsH[64][32];
  float binsE[64][16];
  float rowm[64], rowl[64], rowscale[64];
  unsigned short de[64][128];
};

__global__ __launch_bounds__(512) void fused_attn(
    const float* __restrict__ vhe, const float* __restrict__ vee) {
  extern __shared__ char smem_raw[];
  FSmem& sm = *reinterpret_cast<FSmem*>(smem_raw);
  const int bh = blockIdx.x, b = bh >> 3, h = bh & 7;
  const int i0 = blockIdx.y * 64;
  const int tid = threadIdx.x;
  const int lane = tid & 31, wid = tid >> 5;
  const int g = lane >> 2, t4 = lane & 3;
  // QK warp layout: 4x4, tile 16 rows x 32 cols
  const int wmq = wid & 3, wnq = wid >> 2;
  // AV warp layout: 4x4, tile 16 rows x 16 cols
  const int wma = wid & 3, wna = wid >> 2;

  // ---- init loads ----
  for (int i = tid; i < 64 * 16; i += 512) {
    const int r = i >> 4, cc = (i & 15) * 4;
    float4 q = *reinterpret_cast<const float4*>(&g_Qh[(bh * S + i0 + r) * DK + cc]);
    sm.Qs[r][cc] = to_tf32(q.x); sm.Qs[r][cc + 1] = to_tf32(q.y);
    sm.Qs[r][cc + 2] = to_tf32(q.z); sm.Qs[r][cc + 3] = to_tf32(q.w);
  }
  for (int i = tid; i < 64 * 8; i += 512) {
    const int r = i >> 3, cc = (i & 7) * 4;
    *reinterpret_cast<float4*>(&sm.rowhop[r][cc]) =
        *reinterpret_cast<const float4*>(&g_QHop[(bh * S + i0 + r) * TH + cc]);
  }
  for (int i = tid; i < 64 * 4; i += 512) {
    const int r = i >> 2, cc = (i & 3) * 4;
    *reinterpret_cast<float4*>(&sm.rowedge[r][cc]) =
        *reinterpret_cast<const float4*>(&g_EB[(bh * S + i0 + r) * TE + cc]);
  }
  for (int i = tid; i < 64 * 32; i += 512) sm.binsH[i >> 5][i & 31] = 0.f;
  for (int i = tid; i < 64 * 16; i += 512) sm.binsE[i >> 4][i & 15] = 0.f;
  if (tid < 64) { sm.rowm[tid] = -1e30f; sm.rowl[tid] = 0.f; }

  float co[4][4] = {};  // AV accumulator: [ni<2 used? no: 4 n-tiles? see below]
  // AV warp tile is 16x16 -> co[2][4]; we allocate [4][4] and use [0..1]
  // (kept uniform-size for the epilogue bins mma which reuses co[0..1] too)

  const int rrq = wmq * 16 + g;
  const int rra = wma * 16 + g;

  for (int ch = 0; ch < 4; ch++) {
    const int j0 = ch * 128;
    // ---- chunk loads ----
    for (int i = tid; i < 128 * 16; i += 512) {
      const int r = i >> 4, cc = (i & 15) * 4;
      float4 k = *reinterpret_cast<const float4*>(&g_Kh[(bh * S + j0 + r) * DK + cc]);
      float4 v = *reinterpret_cast<const float4*>(&g_Vh[(bh * S + j0 + r) * DK + cc]);
      sm.Ks[r][cc] = to_tf32(k.x); sm.Ks[r][cc + 1] = to_tf32(k.y);
      sm.Ks[r][cc + 2] = to_tf32(k.z); sm.Ks[r][cc + 3] = to_tf32(k.w);
      sm.Vs[r][cc] = to_tf32(v.x); sm.Vs[r][cc + 1] = to_tf32(v.y);
      sm.Vs[r][cc + 2] = to_tf32(v.z); sm.Vs[r][cc + 3] = to_tf32(v.w);
    }
    for (int i = tid; i < 128 * 8; i += 512) {
      const int r = i >> 3, cc = (i & 7) * 4;
      *reinterpret_cast<float4*>(&sm.KHs[r][cc]) =
          *reinterpret_cast<const float4*>(&g_KHop[(bh * S + j0 + r) * TH + cc]);
    }
    for (int i = tid; i < 64 * 16; i += 512) {
      const int r = i >> 4, c8 = (i & 15) * 8;
      const size_t base = ((size_t)b * S + i0 + r) * S + j0 + c8;
      *reinterpret_cast<uint4*>(&sm.de[r][c8]) =
          *reinterpret_cast<const uint4*>(&g_DE16[base]);
    }
    __syncthreads();

    // ---- QK mma ----
    float cq[4][4] = {};
#pragma unroll
    for (int k8 = 0; k8 < 8; k8++) {
      const int kk = k8 * 8;
      float a[4], bf[4][2];
      a[0] = sm.Qs[rrq][kk + t4];     a[1] = sm.Qs[rrq + 8][kk + t4];
      a[2] = sm.Qs[rrq][kk + t4 + 4]; a[3] = sm.Qs[rrq + 8][kk + t4 + 4];
#pragma unroll
      for (int ni = 0; ni < 4; ni++) {
        const int jl = wnq * 32 + ni * 8 + g;
        bf[ni][0] = sm.Ks[jl][kk + t4]; bf[ni][1] = sm.Ks[jl][kk + t4 + 4];
      }
#pragma unroll
      for (int ni = 0; ni < 4; ni++) mma_tf32(cq[ni], a, bf[ni]);
    }
    // epilogue: bias gather + scale, write scores to Sc
#pragma unroll
    for (int ni = 0; ni < 4; ni++)
#pragma unroll
      for (int fi = 0; fi < 4; fi++) {
        const int row = wmq * 16 + g + ((fi >= 2) ? 8 : 0);
        const int jl = wnq * 32 + ni * 8 + t4 * 2 + (fi & 1);
        const unsigned de = sm.de[row][jl];
        const int dh = de & 0xFF, ee = de >> 8;
        sm.Sc[row][jl] =
            (cq[ni][fi] + sm.rowhop[row][dh] + sm.KHs[jl][dh] + sm.rowedge[row][ee]) * SC2;
      }
    __syncthreads();

    // ---- online softmax + bins (8 threads per row) ----
    {
      const int r = tid >> 3, l8 = tid & 7;
      float cmax = -1e30f;
#pragma unroll
      for (int q = 0; q < 16; q++) cmax = fmaxf(cmax, sm.Sc[r][l8 + 8 * q]);
#pragma unroll
      for (int off = 4; off > 0; off >>= 1)
        cmax = fmaxf(cmax, __shfl_xor_sync(0xffffffffu, cmax, off));
      const float mold = sm.rowm[r];
      const float mnew = fmaxf(mold, cmax);
      const float factor = fast_exp2(mold - mnew);
      // rescale bins for this row
#pragma unroll
      for (int t = l8 * 4; t < l8 * 4 + 4; t++) sm.binsH[r][t] *= factor;
#pragma unroll
      for (int t = l8 * 2; t < l8 * 2 + 2; t++) sm.binsE[r][t] *= factor;
      __syncwarp();
      float lsum = 0.f;
#pragma unroll
      for (int q = 0; q < 16; q++) {
        const int j = l8 + 8 * q;
        const float p = fast_exp2(sm.Sc[r][j] - mnew);
        lsum += p;
        const unsigned de = sm.de[r][j];
        atomicAdd(&sm.binsH[r][de & 0xFF], p);
        atomicAdd(&sm.binsE[r][de >> 8], p);
        sm.Sc[r][j] = to_tf32(p);
      }
#pragma unroll
      for (int off = 4; off > 0; off >>= 1) lsum += __shfl_xor_sync(0xffffffffu, lsum, off);
      if (l8 == 0) {
        sm.rowl[r] = sm.rowl[r] * factor + lsum;
        sm.rowm[r] = mnew;
        sm.rowscale[r] = factor;
      }
    }
    __syncthreads();

    // ---- rescale O accumulator, then P@V mma ----
    {
      const float f0 = sm.rowscale[rra];
      const float f1 = sm.rowscale[rra + 8];
#pragma unroll
      for (int ni = 0; ni < 2; ni++) {
        co[ni][0] *= f0; co[ni][1] *= f0;
        co[ni][2] *= f1; co[ni][3] *= f1;
      }
    }
#pragma unroll
    for (int ks = 0; ks < 16; ks++) {
      const int kk = ks * 8;
      float a[4], bf[2][2];
      a[0] = sm.Sc[rra][kk + t4];     a[1] = sm.Sc[rra + 8][kk + t4];
      a[2] = sm.Sc[rra][kk + t4 + 4]; a[3] = sm.Sc[rra + 8][kk + t4 + 4];
#pragma unroll
      for (int ni = 0; ni < 2; ni++) {
        const int cc = wna * 16 + ni * 8 + g;
        bf[ni][0] = sm.Vs[kk + t4][cc]; bf[ni][1] = sm.Vs[kk + t4 + 4][cc];
      }
#pragma unroll
      for (int ni = 0; ni < 2; ni++) mma_tf32(co[ni], a, bf[ni]);
    }
    __syncthreads();
  }

  // ---- epilogue: bins GEMMs accumulate into co, normalize, store ----
  for (int i = tid; i < 64 * 32; i += 512) {
    const int r = i >> 5, t = i & 31;
    sm.Sc[r][t] = to_tf32(sm.binsH[r][t]);
  }
  for (int i = tid; i < 64 * 16; i += 512) {
    const int r = i >> 4, t = i & 15;
    sm.Sc[r][32 + t] = to_tf32(sm.binsE[r][t]);
  }
  for (int i = tid; i < 48 * 16; i += 512) {
    const int t = i >> 4, cc = (i & 15) * 4;
    const float* src = (t < TH) ? &vhe[t * HID + h * DK + cc]
                                : &vee[(t - TH) * HID + h * DK + cc];
    float4 v = *reinterpret_cast<const float4*>(src);
    sm.Vs[t][cc] = to_tf32(v.x); sm.Vs[t][cc + 1] = to_tf32(v.y);
    sm.Vs[t][cc + 2] = to_tf32(v.z); sm.Vs[t][cc + 3] = to_tf32(v.w);
  }
  __syncthreads();
#pragma unroll
  for (int ks = 0; ks < 6; ks++) {
    const int kk = ks * 8;
    float a[4], bf[2][2];
    a[0] = sm.Sc[rra][kk + t4];     a[1] = sm.Sc[rra + 8][kk + t4];
    a[2] = sm.Sc[rra][kk + t4 + 4]; a[3] = sm.Sc[rra + 8][kk + t4 + 4];
#pragma unroll
    for (int ni = 0; ni < 2; ni++) {
      const int cc = wna * 16 + ni * 8 + g;
      bf[ni][0] = sm.Vs[kk + t4][cc]; bf[ni][1] = sm.Vs[kk + t4 + 4][cc];
    }
#pragma unroll
    for (int ni = 0; ni < 2; ni++) mma_tf32(co[ni], a, bf[ni]);
  }

  const float inv0 = 1.f / sm.rowl[rra];
  const float inv1 = 1.f / sm.rowl[rra + 8];
#pragma unroll
  for (int ni = 0; ni < 2; ni++)
#pragma unroll
    for (int fi = 0; fi < 4; fi++) {
      const int row = i0 + wma * 16 + g + ((fi >= 2) ? 8 : 0);
      const int col = wna * 16 + ni * 8 + t4 * 2 + (fi & 1);
      g_OutH[(bh * S + row) * DK + col] = co[ni][fi] * ((fi >= 2) ? inv1 : inv0);
    }
}

// ---------------- launcher ----------------------------------------------------
extern "C" void kernel_launch(void* const* d_in, const int* in_sizes, int n_in,
                              void* d_out, int out_size) {
  (void)in_sizes; (void)n_in; (void)out_size;
  const float* q   = (const float*)d_in[0];
  const float* k   = (const float*)d_in[1];
  const float* v   = (const float*)d_in[2];
  const float* qhe = (const float*)d_in[3];
  const float* qee = (const float*)d_in[4];
  const float* khe = (const float*)d_in[5];
  const float* kee = (const float*)d_in[6];
  const float* vhe = (const float*)d_in[7];
  const float* vee = (const float*)d_in[8];
  const int* dist  = (const int*)d_in[9];
  const int* edge  = (const int*)d_in[10];
  const float* Wq = (const float*)d_in[11], *bq = (const float*)d_in[12];
  const float* Wk = (const float*)d_in[13], *bk = (const float*)d_in[14];
  const float* Wv = (const float*)d_in[15], *bv = (const float*)d_in[16];
  const float* Wo = (const float*)d_in[17], *bo = (const float*)d_in[18];
  float* out = (float*)d_out;

  const int tables_smem = 224 * 68 * 4;
  const int fused_smem = (int)sizeof(FSmem);
  cudaFuncSetAttribute(tables_mma, cudaFuncAttributeMaxDynamicSharedMemorySize, tables_smem);
  cudaFuncSetAttribute(fused_attn, cudaFuncAttributeMaxDynamicSharedMemorySize, fused_smem);

  const size_t n4 = (size_t)B * S * S / 4;
  pack_kernel<<<(int)((n4 + 255) / 256), 256>>>(dist, edge);

  const dim3 gp(8, 64);  // N/64, M/128
  proj_mma<0><<<gp, 256>>>(q, Wq, bq, nullptr);
  proj_mma<1><<<gp, 256>>>(k, Wk, bk, nullptr);
  proj_mma<2><<<gp, 256>>>(v, Wv, bv, nullptr);
  tables_mma<<<dim3(BH, 8), 256, tables_smem>>>(qhe, qee, khe, kee);
  fused_attn<<<dim3(BH, 8), 512, fused_smem>>>(vhe, vee);
  proj_mma<3><<<gp, 256>>>(nullptr, Wo, bo, out);
}

// round 4
// speedup vs baseline: 2.7818x; 1.1541x over previous
#include <cuda_runtime.h>
#include <cuda_fp16.h>

namespace {
constexpr int B = 16, S = 512, HID = 512, NH = 8, DK = 64, TH = 32, TE = 16;
constexpr int BH = B * NH;            // 128
constexpr float SC2 = 0.125f * 1.44269504088896f;  // scale * log2(e)
}

// ---------------- scratch (device globals; no runtime allocation) -------------
__device__ __half g_Qh[BH * S * DK];
__device__ __half g_Kh[BH * S * DK];
__device__ __half g_VhT[BH * DK * S];                // V transposed: [bh][d][s]
__device__ float  g_QHop[BH * S * TH];
__device__ float  g_KHop[BH * S * TH];
__device__ float  g_EB[BH * S * TE];                 // QEdge + KEdge (row-indexed)
__device__ __half g_OutH[BH * S * DK];
__device__ unsigned short g_DE16[(size_t)B * S * S]; // packed dist|edge<<8

// ---------------- helpers -----------------------------------------------------
__device__ __forceinline__ unsigned pack_half2(float x, float y) {
  __half2 h = __floats2half2_rn(x, y);
  return *reinterpret_cast<unsigned*>(&h);
}
__device__ __forceinline__ float fast_exp2(float x) {
  asm("ex2.approx.f32 %0, %0;" : "+f"(x));
  return x;
}
// D(f32,16x8) += A(16x16 f16,row) * B(16x8 f16,col)
__device__ __forceinline__ void mma_f16(float* c, const unsigned* a, const unsigned* b) {
  asm volatile(
      "mma.sync.aligned.m16n8k16.row.col.f32.f16.f16.f32 "
      "{%0,%1,%2,%3}, {%4,%5,%6,%7}, {%8,%9}, {%0,%1,%2,%3};\n"
      : "+f"(c[0]), "+f"(c[1]), "+f"(c[2]), "+f"(c[3])
      : "r"(a[0]), "r"(a[1]), "r"(a[2]), "r"(a[3]), "r"(b[0]), "r"(b[1]));
}

// ---------------- pack dist/edge into uint16 ----------------------------------
__global__ __launch_bounds__(256) void pack_kernel(const int* __restrict__ dist,
                                                   const int* __restrict__ edge) {
  const size_t i = (size_t)blockIdx.x * 256 + threadIdx.x;
  const size_t n4 = (size_t)B * S * S / 4;
  if (i >= n4) return;
  int4 d = reinterpret_cast<const int4*>(dist)[i];
  int4 e = reinterpret_cast<const int4*>(edge)[i];
  ushort4 o;
  o.x = (unsigned short)(d.x | (e.x << 8));
  o.y = (unsigned short)(d.y | (e.y << 8));
  o.z = (unsigned short)(d.z | (e.z << 8));
  o.w = (unsigned short)(d.w | (e.w << 8));
  reinterpret_cast<ushort4*>(g_DE16)[i] = o;
}

// ---------------- proj GEMM: C = A @ W^T + bias (fp16 mma) --------------------
// TGT 0: ->g_Qh  1: ->g_Kh  2: ->g_VhT (transposed)  3: g_OutH -> Cout (f32)
template <int TGT>
__global__ __launch_bounds__(256) void proj_mma(
    const float* __restrict__ A, const float* __restrict__ W,
    const float* __restrict__ bias, float* __restrict__ Cout) {
  __shared__ unsigned As[128][20];   // 32 halves (16 words) + pad
  __shared__ unsigned Ws[64][20];
  const int m0 = blockIdx.y * 128, n0 = blockIdx.x * 64;
  const int tid = threadIdx.x;
  const int lane = tid & 31, wid = tid >> 5;
  const int wm = wid & 3, wn = wid >> 2;   // warp tile: 32 rows x 32 cols
  const int g = lane >> 2, t4 = lane & 3;
  float c[2][4][4] = {};

  for (int k0 = 0; k0 < 512; k0 += 32) {
    {  // A: 128x32 floats, 2 threads/row
      const int r = tid >> 1, cb = (tid & 1) * 16;
#pragma unroll
      for (int i = 0; i < 4; i++) {
        const int cc = cb + i * 4;
        if (TGT < 3) {
          float4 v = *reinterpret_cast<const float4*>(&A[(m0 + r) * 512 + k0 + cc]);
          As[r][(cc >> 1)]     = pack_half2(v.x, v.y);
          As[r][(cc >> 1) + 1] = pack_half2(v.z, v.w);
        } else {
          const int n = m0 + r, kk = k0 + cc;
          const int bb = n >> 9, ii = n & 511, h = kk >> 6, d = kk & 63;
          uint2 v = *reinterpret_cast<const uint2*>(
              &g_OutH[(((bb * NH + h) * S) + ii) * DK + d]);
          As[r][(cc >> 1)] = v.x;
          As[r][(cc >> 1) + 1] = v.y;
        }
      }
    }
    {  // W: 64x32 floats, 4 threads/row
      const int r = tid >> 2, cb = (tid & 3) * 8;
#pragma unroll
      for (int i = 0; i < 2; i++) {
        const int cc = cb + i * 4;
        float4 v = *reinterpret_cast<const float4*>(&W[(n0 + r) * 512 + k0 + cc]);
        Ws[r][(cc >> 1)]     = pack_half2(v.x, v.y);
        Ws[r][(cc >> 1) + 1] = pack_half2(v.z, v.w);
      }
    }
    __syncthreads();
#pragma unroll
    for (int k16 = 0; k16 < 2; k16++) {
      const int kw = k16 * 8;
      unsigned a[2][4], b[4][2];
#pragma unroll
      for (int mi = 0; mi < 2; mi++) {
        const int rr = wm * 32 + mi * 16 + g;
        a[mi][0] = As[rr][kw + t4];     a[mi][1] = As[rr + 8][kw + t4];
        a[mi][2] = As[rr][kw + 4 + t4]; a[mi][3] = As[rr + 8][kw + 4 + t4];
      }
#pragma unroll
      for (int ni = 0; ni < 4; ni++) {
        const int cc = wn * 32 + ni * 8 + g;
        b[ni][0] = Ws[cc][kw + t4]; b[ni][1] = Ws[cc][kw + 4 + t4];
      }
#pragma unroll
      for (int mi = 0; mi < 2; mi++)
#pragma unroll
        for (int ni = 0; ni < 4; ni++) mma_f16(c[mi][ni], a[mi], b[ni]);
    }
    __syncthreads();
  }

#pragma unroll
  for (int mi = 0; mi < 2; mi++)
#pragma unroll
    for (int ni = 0; ni < 4; ni++) {
#pragma unroll
      for (int half_i = 0; half_i < 2; half_i++) {
        const int row = m0 + wm * 32 + mi * 16 + g + half_i * 8;
        const int col = n0 + wn * 32 + ni * 8 + t4 * 2;
        const float v0 = c[mi][ni][half_i * 2 + 0] + bias[col];
        const float v1 = c[mi][ni][half_i * 2 + 1] + bias[col + 1];
        if (TGT == 3) {
          *reinterpret_cast<float2*>(&Cout[row * 512 + col]) = make_float2(v0, v1);
        } else {
          const int bb = row >> 9, ii = row & 511, h = col >> 6, d = col & 63;
          if (TGT == 2) {
            g_VhT[((bb * NH + h) * DK + d) * S + ii]     = __float2half_rn(v0);
            g_VhT[((bb * NH + h) * DK + d + 1) * S + ii] = __float2half_rn(v1);
          } else {
            __half* dst = (TGT == 0) ? g_Qh : g_Kh;
            *reinterpret_cast<__half2*>(&dst[(((bb * NH + h) * S) + ii) * DK + d]) =
                __floats2half2_rn(v0, v1);
          }
        }
      }
    }
}

// ---------------- tables: QHop/KHop/EB via fp16 mma ---------------------------
__global__ __launch_bounds__(256) void tables_mma(
    const float* __restrict__ qhe, const float* __restrict__ qee,
    const float* __restrict__ khe, const float* __restrict__ kee) {
  __shared__ unsigned Qs[64][36];   // 64 halves (32 words) + pad
  __shared__ unsigned Ks2[64][36];
  __shared__ unsigned Eq[48][36];
  __shared__ unsigned Ek[48][36];
  const int bh = blockIdx.x, h = bh & 7;
  const int i0 = blockIdx.y * 64;
  const int tid = threadIdx.x;
  const int lane = tid & 31, wid = tid >> 5;
  const int wm = wid & 3, wn = wid >> 2;  // warp: 16 rows x 24 cols
  const int g = lane >> 2, t4 = lane & 3;

  for (int i = tid; i < 64 * 16; i += 256) {  // 16 uint2 per row
    const int r = i >> 4, u = i & 15;
    uint2 q = *reinterpret_cast<const uint2*>(&g_Qh[(bh * S + i0 + r) * DK + u * 4]);
    uint2 k = *reinterpret_cast<const uint2*>(&g_Kh[(bh * S + i0 + r) * DK + u * 4]);
    Qs[r][u * 2] = q.x;  Qs[r][u * 2 + 1] = q.y;
    Ks2[r][u * 2] = k.x; Ks2[r][u * 2 + 1] = k.y;
  }
  for (int i = tid; i < 48 * 16; i += 256) {
    const int r = i >> 4, cc = (i & 15) * 4;
    const float* sq = (r < TH) ? &qhe[r * HID + h * DK + cc] : &qee[(r - TH) * HID + h * DK + cc];
    const float* sk = (r < TH) ? &khe[r * HID + h * DK + cc] : &kee[(r - TH) * HID + h * DK + cc];
    float4 vq = *reinterpret_cast<const float4*>(sq);
    float4 vk = *reinterpret_cast<const float4*>(sk);
    Eq[r][(cc >> 1)]     = pack_half2(vq.x, vq.y);
    Eq[r][(cc >> 1) + 1] = pack_half2(vq.z, vq.w);
    Ek[r][(cc >> 1)]     = pack_half2(vk.x, vk.y);
    Ek[r][(cc >> 1) + 1] = pack_half2(vk.z, vk.w);
  }
  __syncthreads();

  float cQ[3][4] = {}, cK[3][4] = {};
#pragma unroll
  for (int ks = 0; ks < 4; ks++) {
    const int kw = ks * 8;
    const int rr = wm * 16 + g;
    unsigned aQ[4], aK[4], bQ[3][2], bK[3][2];
    aQ[0] = Qs[rr][kw + t4];      aQ[1] = Qs[rr + 8][kw + t4];
    aQ[2] = Qs[rr][kw + 4 + t4];  aQ[3] = Qs[rr + 8][kw + 4 + t4];
    aK[0] = Ks2[rr][kw + t4];     aK[1] = Ks2[rr + 8][kw + t4];
    aK[2] = Ks2[rr][kw + 4 + t4]; aK[3] = Ks2[rr + 8][kw + 4 + t4];
#pragma unroll
    for (int ni = 0; ni < 3; ni++) {
      const int cc = wn * 24 + ni * 8 + g;
      bQ[ni][0] = Eq[cc][kw + t4]; bQ[ni][1] = Eq[cc][kw + 4 + t4];
      bK[ni][0] = Ek[cc][kw + t4]; bK[ni][1] = Ek[cc][kw + 4 + t4];
    }
#pragma unroll
    for (int ni = 0; ni < 3; ni++) {
      mma_f16(cQ[ni], aQ, bQ[ni]);
      mma_f16(cK[ni], aK, bK[ni]);
    }
  }
#pragma unroll
  for (int ni = 0; ni < 3; ni++)
#pragma unroll
    for (int fi = 0; fi < 4; fi++) {
      const int row = i0 + wm * 16 + g + ((fi >= 2) ? 8 : 0);
      const int col = wn * 24 + ni * 8 + t4 * 2 + (fi & 1);
      if (col < TH) {
        g_QHop[(bh * S + row) * TH + col] = cQ[ni][fi];
        g_KHop[(bh * S + row) * TH + col] = cK[ni][fi];
      } else {
        g_EB[(bh * S + row) * TE + (col - TH)] = cQ[ni][fi] + cK[ni][fi];
      }
    }
}

// ---------------- fused flash attention + bins (fp16 mma) ---------------------
struct FSmem {
  float Sc[64][132];          // f32 scores
  unsigned Ph[64][68];        // half P (fragment source for AV; bins in epilogue)
  unsigned Ks[128][36];       // K chunk (64 halves/row + pad)
  unsigned Vt[64][68];        // V^T chunk: [d][j] halves (also tables in epilogue)
  unsigned Qs[64][36];
  float KHs[128][36];
  float rowhop[64][32];
  float rowedge[64][16];
  float binsH[64][32];
  float binsE[64][16];
  float rowm[64], rowl[64], rowscale[64];
  unsigned short de[64][128];
};

__global__ __launch_bounds__(512) void fused_attn(
    const float* __restrict__ vhe, const float* __restrict__ vee) {
  extern __shared__ char smem_raw[];
  FSmem& sm = *reinterpret_cast<FSmem*>(smem_raw);
  const int bh = blockIdx.x, b = bh >> 3, h = bh & 7;
  const int i0 = blockIdx.y * 64;
  const int tid = threadIdx.x;
  const int lane = tid & 31, wid = tid >> 5;
  const int g = lane >> 2, t4 = lane & 3;
  const int wmq = wid & 3, wnq = wid >> 2;  // QK: 16 rows x 32 cols
  const int wma = wid & 3, wna = wid >> 2;  // AV: 16 rows x 16 cols

  // ---- init loads ----
  for (int i = tid; i < 64 * 16; i += 512) {
    const int r = i >> 4, u = i & 15;
    uint2 q = *reinterpret_cast<const uint2*>(&g_Qh[(bh * S + i0 + r) * DK + u * 4]);
    sm.Qs[r][u * 2] = q.x; sm.Qs[r][u * 2 + 1] = q.y;
  }
  for (int i = tid; i < 64 * 8; i += 512) {
    const int r = i >> 3, cc = (i & 7) * 4;
    *reinterpret_cast<float4*>(&sm.rowhop[r][cc]) =
        *reinterpret_cast<const float4*>(&g_QHop[(bh * S + i0 + r) * TH + cc]);
  }
  for (int i = tid; i < 64 * 4; i += 512) {
    const int r = i >> 2, cc = (i & 3) * 4;
    *reinterpret_cast<float4*>(&sm.rowedge[r][cc]) =
        *reinterpret_cast<const float4*>(&g_EB[(bh * S + i0 + r) * TE + cc]);
  }
  for (int i = tid; i < 64 * 32; i += 512) sm.binsH[i >> 5][i & 31] = 0.f;
  for (int i = tid; i < 64 * 16; i += 512) sm.binsE[i >> 4][i & 15] = 0.f;
  if (tid < 64) { sm.rowm[tid] = -1e30f; sm.rowl[tid] = 0.f; }

  float co[2][4] = {};
  const int rrq = wmq * 16 + g;
  const int rra = wma * 16 + g;

  for (int ch = 0; ch < 4; ch++) {
    const int j0 = ch * 128;
    // ---- chunk loads ----
    for (int i = tid; i < 128 * 16; i += 512) {
      const int r = i >> 4, u = i & 15;
      uint2 k = *reinterpret_cast<const uint2*>(&g_Kh[(bh * S + j0 + r) * DK + u * 4]);
      sm.Ks[r][u * 2] = k.x; sm.Ks[r][u * 2 + 1] = k.y;
    }
    for (int i = tid; i < 64 * 32; i += 512) {
      const int d = i >> 5, u = i & 31;
      uint2 v = *reinterpret_cast<const uint2*>(&g_VhT[(bh * DK + d) * S + j0 + u * 4]);
      sm.Vt[d][u * 2] = v.x; sm.Vt[d][u * 2 + 1] = v.y;
    }
    for (int i = tid; i < 128 * 8; i += 512) {
      const int r = i >> 3, cc = (i & 7) * 4;
      *reinterpret_cast<float4*>(&sm.KHs[r][cc]) =
          *reinterpret_cast<const float4*>(&g_KHop[(bh * S + j0 + r) * TH + cc]);
    }
    for (int i = tid; i < 64 * 16; i += 512) {
      const int r = i >> 4, c8 = (i & 15) * 8;
      const size_t base = ((size_t)b * S + i0 + r) * S + j0 + c8;
      *reinterpret_cast<uint4*>(&sm.de[r][c8]) =
          *reinterpret_cast<const uint4*>(&g_DE16[base]);
    }
    __syncthreads();

    // ---- QK mma (k = 64 halves -> 4 k16 steps) ----
    float cq[4][4] = {};
#pragma unroll
    for (int ks = 0; ks < 4; ks++) {
      const int kw = ks * 8;
      unsigned a[4], bf[4][2];
      a[0] = sm.Qs[rrq][kw + t4];     a[1] = sm.Qs[rrq + 8][kw + t4];
      a[2] = sm.Qs[rrq][kw + 4 + t4]; a[3] = sm.Qs[rrq + 8][kw + 4 + t4];
#pragma unroll
      for (int ni = 0; ni < 4; ni++) {
        const int jl = wnq * 32 + ni * 8 + g;
        bf[ni][0] = sm.Ks[jl][kw + t4]; bf[ni][1] = sm.Ks[jl][kw + 4 + t4];
      }
#pragma unroll
      for (int ni = 0; ni < 4; ni++) mma_f16(cq[ni], a, bf[ni]);
    }
    // epilogue: bias gather + scale, write scores to Sc (f32)
#pragma unroll
    for (int ni = 0; ni < 4; ni++)
#pragma unroll
      for (int fi = 0; fi < 4; fi++) {
        const int row = wmq * 16 + g + ((fi >= 2) ? 8 : 0);
        const int jl = wnq * 32 + ni * 8 + t4 * 2 + (fi & 1);
        const unsigned de = sm.de[row][jl];
        const int dh = de & 0xFF, ee = de >> 8;
        sm.Sc[row][jl] =
            (cq[ni][fi] + sm.rowhop[row][dh] + sm.KHs[jl][dh] + sm.rowedge[row][ee]) * SC2;
      }
    __syncthreads();

    // ---- online softmax + bins (8 threads per row) ----
    {
      const int r = tid >> 3, l8 = tid & 7;
      float cmax = -1e30f;
#pragma unroll
      for (int q = 0; q < 16; q++) cmax = fmaxf(cmax, sm.Sc[r][l8 + 8 * q]);
#pragma unroll
      for (int off = 4; off > 0; off >>= 1)
        cmax = fmaxf(cmax, __shfl_xor_sync(0xffffffffu, cmax, off));
      const float mold = sm.rowm[r];
      const float mnew = fmaxf(mold, cmax);
      const float factor = fast_exp2(mold - mnew);
#pragma unroll
      for (int t = l8 * 4; t < l8 * 4 + 4; t++) sm.binsH[r][t] *= factor;
#pragma unroll
      for (int t = l8 * 2; t < l8 * 2 + 2; t++) sm.binsE[r][t] *= factor;
      __syncwarp();
      float lsum = 0.f;
      __half* phrow = reinterpret_cast<__half*>(&sm.Ph[r][0]);
#pragma unroll
      for (int q = 0; q < 16; q++) {
        const int j = l8 + 8 * q;
        const float p = fast_exp2(sm.Sc[r][j] - mnew);
        lsum += p;
        const unsigned de = sm.de[r][j];
        atomicAdd(&sm.binsH[r][de & 0xFF], p);
        atomicAdd(&sm.binsE[r][de >> 8], p);
        phrow[j] = __float2half_rn(p);
      }
#pragma unroll
      for (int off = 4; off > 0; off >>= 1) lsum += __shfl_xor_sync(0xffffffffu, lsum, off);
      if (l8 == 0) {
        sm.rowl[r] = sm.rowl[r] * factor + lsum;
        sm.rowm[r] = mnew;
        sm.rowscale[r] = factor;
      }
    }
    __syncthreads();

    // ---- rescale O accumulator, then P@V mma (k = 128 halves -> 8 k16) ----
    {
      const float f0 = sm.rowscale[rra];
      const float f1 = sm.rowscale[rra + 8];
#pragma unroll
      for (int ni = 0; ni < 2; ni++) {
        co[ni][0] *= f0; co[ni][1] *= f0;
        co[ni][2] *= f1; co[ni][3] *= f1;
      }
    }
#pragma unroll
    for (int ks = 0; ks < 8; ks++) {
      const int kw = ks * 8;
      unsigned a[4], bf[2][2];
      a[0] = sm.Ph[rra][kw + t4];     a[1] = sm.Ph[rra + 8][kw + t4];
      a[2] = sm.Ph[rra][kw + 4 + t4]; a[3] = sm.Ph[rra + 8][kw + 4 + t4];
#pragma unroll
      for (int ni = 0; ni < 2; ni++) {
        const int cc = wna * 16 + ni * 8 + g;
        bf[ni][0] = sm.Vt[cc][kw + t4]; bf[ni][1] = sm.Vt[cc][kw + 4 + t4];
      }
#pragma unroll
      for (int ni = 0; ni < 2; ni++) mma_f16(co[ni], a, bf[ni]);
    }
    __syncthreads();
  }

  // ---- epilogue: bins GEMMs accumulate into co, normalize, store ----
  for (int i = tid; i < 64 * 48; i += 512) {
    const int r = i / 48, t = i % 48;
    const float v = (t < TH) ? sm.binsH[r][t] : sm.binsE[r][t - TH];
    reinterpret_cast<__half*>(&sm.Ph[r][0])[t] = __float2half_rn(v);
  }
  for (int i = tid; i < 64 * 24; i += 512) {  // tables transposed into Vt[d][t]
    const int d = i / 24, tw = i % 24;
    const int t0 = tw * 2, t1 = t0 + 1;
    const float x = (t0 < TH) ? vhe[t0 * HID + h * DK + d] : vee[(t0 - TH) * HID + h * DK + d];
    const float y = (t1 < TH) ? vhe[t1 * HID + h * DK + d] : vee[(t1 - TH) * HID + h * DK + d];
    sm.Vt[d][tw] = pack_half2(x, y);
  }
  __syncthreads();
#pragma unroll
  for (int ks = 0; ks < 3; ks++) {  // k = 48 halves -> 3 k16 steps
    const int kw = ks * 8;
    unsigned a[4], bf[2][2];
    a[0] = sm.Ph[rra][kw + t4];     a[1] = sm.Ph[rra + 8][kw + t4];
    a[2] = sm.Ph[rra][kw + 4 + t4]; a[3] = sm.Ph[rra + 8][kw + 4 + t4];
#pragma unroll
    for (int ni = 0; ni < 2; ni++) {
      const int cc = wna * 16 + ni * 8 + g;
      bf[ni][0] = sm.Vt[cc][kw + t4]; bf[ni][1] = sm.Vt[cc][kw + 4 + t4];
    }
#pragma unroll
    for (int ni = 0; ni < 2; ni++) mma_f16(co[ni], a, bf[ni]);
  }

  const float inv0 = 1.f / sm.rowl[rra];
  const float inv1 = 1.f / sm.rowl[rra + 8];
#pragma unroll
  for (int ni = 0; ni < 2; ni++) {
    const int col = wna * 16 + ni * 8 + t4 * 2;
    const int row0 = i0 + wma * 16 + g;
    *reinterpret_cast<__half2*>(&g_OutH[(bh * S + row0) * DK + col]) =
        __floats2half2_rn(co[ni][0] * inv0, co[ni][1] * inv0);
    *reinterpret_cast<__half2*>(&g_OutH[(bh * S + row0 + 8) * DK + col]) =
        __floats2half2_rn(co[ni][2] * inv1, co[ni][3] * inv1);
  }
}

// ---------------- launcher ----------------------------------------------------
extern "C" void kernel_launch(void* const* d_in, const int* in_sizes, int n_in,
                              void* d_out, int out_size) {
  (void)in_sizes; (void)n_in; (void)out_size;
  const float* q   = (const float*)d_in[0];
  const float* k   = (const float*)d_in[1];
  const float* v   = (const float*)d_in[2];
  const float* qhe = (const float*)d_in[3];
  const float* qee = (const float*)d_in[4];
  const float* khe = (const float*)d_in[5];
  const float* kee = (const float*)d_in[6];
  const float* vhe = (const float*)d_in[7];
  const float* vee = (const float*)d_in[8];
  const int* dist  = (const int*)d_in[9];
  const int* edge  = (const int*)d_in[10];
  const float* Wq = (const float*)d_in[11], *bq = (const float*)d_in[12];
  const float* Wk = (const float*)d_in[13], *bk = (const float*)d_in[14];
  const float* Wv = (const float*)d_in[15], *bv = (const float*)d_in[16];
  const float* Wo = (const float*)d_in[17], *bo = (const float*)d_in[18];
  float* out = (float*)d_out;

  const int fused_smem = (int)sizeof(FSmem);
  cudaFuncSetAttribute(fused_attn, cudaFuncAttributeMaxDynamicSharedMemorySize, fused_smem);

  const size_t n4 = (size_t)B * S * S / 4;
  pack_kernel<<<(int)((n4 + 255) / 256), 256>>>(dist, edge);

  const dim3 gp(8, 64);  // N/64, M/128
  proj_mma<0><<<gp, 256>>>(q, Wq, bq, nullptr);
  proj_mma<1><<<gp, 256>>>(k, Wk, bk, nullptr);
  proj_mma<2><<<gp, 256>>>(v, Wv, bv, nullptr);
  tables_mma<<<dim3(BH, 8), 256>>>(qhe, qee, khe, kee);
  fused_attn<<<dim3(BH, 8), 512, fused_smem>>>(vhe, vee);
  proj_mma<3><<<gp, 256>>>(nullptr, Wo, bo, out);
}

// round 5
// speedup vs baseline: 3.8718x; 1.3918x over previous
#include <cuda_runtime.h>
#include <cuda_fp16.h>

namespace {
constexpr int B = 16, S = 512, HID = 512, NH = 8, DK = 64, TH = 32, TE = 16;
constexpr int BH = 128;
constexpr float SC2 = 0.125f * 1.44269504088896f;  // scale * log2(e)
constexpr int QN = 8192 * 512;
constexpr int WN = 512 * 512;
}

// ---------------- scratch (device globals; no runtime allocation) -------------
__device__ __half g_In16[3][QN];                     // q,k,v as half
__device__ __half g_W16[4][WN];                      // Wq,Wk,Wv,Wo as half
__device__ __half g_Qh[BH * S * DK];
__device__ __half g_Kh[BH * S * DK];
__device__ __half g_VhT[BH * DK * S];                // V transposed: [bh][d][s]
__device__ float  g_QHop[BH * S * TH];
__device__ float  g_KHop[BH * S * TH];
__device__ float  g_EB[BH * S * TE];
__device__ __half g_OutH[BH * S * DK];
__device__ unsigned short g_DE16[(size_t)B * S * S];

// ---------------- helpers -----------------------------------------------------
__device__ __forceinline__ unsigned pack_half2(float x, float y) {
  __half2 h = __floats2half2_rn(x, y);
  return *reinterpret_cast<unsigned*>(&h);
}
__device__ __forceinline__ float fast_exp2(float x) {
  asm("ex2.approx.f32 %0, %0;" : "+f"(x));
  return x;
}
__device__ __forceinline__ void mma_f16(float* c, const unsigned* a, const unsigned* b) {
  asm volatile(
      "mma.sync.aligned.m16n8k16.row.col.f32.f16.f16.f32 "
      "{%0,%1,%2,%3}, {%4,%5,%6,%7}, {%8,%9}, {%0,%1,%2,%3};\n"
      : "+f"(c[0]), "+f"(c[1]), "+f"(c[2]), "+f"(c[3])
      : "r"(a[0]), "r"(a[1]), "r"(a[2]), "r"(a[3]), "r"(b[0]), "r"(b[1]));
}
__device__ __forceinline__ void cpa16(void* sm, const void* gm) {
  unsigned s = (unsigned)__cvta_generic_to_shared(sm);
  asm volatile("cp.async.ca.shared.global [%0], [%1], 16;\n" :: "r"(s), "l"(gm));
}
__device__ __forceinline__ void cp_commit() { asm volatile("cp.async.commit_group;\n"); }
__device__ __forceinline__ void cp_wait1() { asm volatile("cp.async.wait_group 1;\n"); }
__device__ __forceinline__ void cp_wait0() { asm volatile("cp.async.wait_group 0;\n"); }

// ---------------- convert fp32 inputs/weights to half -------------------------
__global__ __launch_bounds__(256) void convert_kernel(
    const float* __restrict__ q, const float* __restrict__ k, const float* __restrict__ v,
    const float* __restrict__ Wq, const float* __restrict__ Wk,
    const float* __restrict__ Wv, const float* __restrict__ Wo) {
  const int QU = QN / 8, WU = WN / 8;
  const int total = 3 * QU + 4 * WU;
  int i = blockIdx.x * 256 + threadIdx.x;
  if (i >= total) return;
  const float* src; __half* dst; int off;
  if (i < 3 * QU) {
    int z = i / QU; off = (i - z * QU) * 8;
    src = (z == 0) ? q : (z == 1) ? k : v;
    dst = g_In16[z];
  } else {
    int j = i - 3 * QU; int z = j / WU; off = (j - z * WU) * 8;
    src = (z == 0) ? Wq : (z == 1) ? Wk : (z == 2) ? Wv : Wo;
    dst = g_W16[z];
  }
  float4 a = *reinterpret_cast<const float4*>(src + off);
  float4 b2 = *reinterpret_cast<const float4*>(src + off + 4);
  uint4 o;
  o.x = pack_half2(a.x, a.y);  o.y = pack_half2(a.z, a.w);
  o.z = pack_half2(b2.x, b2.y); o.w = pack_half2(b2.z, b2.w);
  *reinterpret_cast<uint4*>(dst + off) = o;
}

// ---------------- pack dist/edge into uint16 ----------------------------------
__global__ __launch_bounds__(256) void pack_kernel(const int* __restrict__ dist,
                                                   const int* __restrict__ edge) {
  const size_t i = (size_t)blockIdx.x * 256 + threadIdx.x;
  const size_t n4 = (size_t)B * S * S / 4;
  if (i >= n4) return;
  int4 d = reinterpret_cast<const int4*>(dist)[i];
  int4 e = reinterpret_cast<const int4*>(edge)[i];
  ushort4 o;
  o.x = (unsigned short)(d.x | (e.x << 8));
  o.y = (unsigned short)(d.y | (e.y << 8));
  o.z = (unsigned short)(d.z | (e.z << 8));
  o.w = (unsigned short)(d.w | (e.w << 8));
  reinterpret_cast<ushort4*>(g_DE16)[i] = o;
}

// ---------------- proj GEMM (double-buffered cp.async, fp16 mma) --------------
// MODE 0: z=blockIdx.z in {0,1,2} -> Qh/Kh/VhT.  MODE 1: out proj (f32 out).
template <int MODE>
__global__ __launch_bounds__(256) void proj_mma(
    const float* __restrict__ bias0, const float* __restrict__ bias1,
    const float* __restrict__ bias2, float* __restrict__ Cout) {
  extern __shared__ __half psm[];
  __half* Abuf[2] = { psm, psm + 128 * 72 };
  __half* Wbuf[2] = { psm + 2 * 128 * 72, psm + 2 * 128 * 72 + 64 * 72 };
  const int z = (MODE == 0) ? blockIdx.z : 3;
  const __half* A = (MODE == 0) ? g_In16[z] : g_OutH;
  const __half* W = g_W16[z];
  const float* bias = (MODE == 0) ? (z == 0 ? bias0 : (z == 1 ? bias1 : bias2)) : bias0;
  const int m0 = blockIdx.y * 128, n0 = blockIdx.x * 64;
  const int tid = threadIdx.x, lane = tid & 31, wid = tid >> 5;
  const int wm = wid & 3, wn = wid >> 2, g = lane >> 2, t4 = lane & 3;
  const int bbM = m0 >> 9, ii0 = m0 & 511;
  float c[2][4][4] = {};

  auto issue = [&](int s, int buf) {
#pragma unroll
    for (int i = 0; i < 4; i++) {
      int idx = tid + i * 256;
      int r = idx >> 3, c8 = (idx & 7) * 8;
      const __half* gp;
      if (MODE == 0) gp = A + (m0 + r) * 512 + s * 64 + c8;
      else {
        int n = m0 + r, bb = n >> 9, ii = n & 511;
        gp = g_OutH + ((bb * NH + s) * S + ii) * DK + c8;
      }
      cpa16(Abuf[buf] + r * 72 + c8, gp);
    }
#pragma unroll
    for (int i = 0; i < 2; i++) {
      int idx = tid + i * 256;
      int r = idx >> 3, c8 = (idx & 7) * 8;
      cpa16(Wbuf[buf] + r * 72 + c8, W + (n0 + r) * 512 + s * 64 + c8);
    }
    cp_commit();
  };

  issue(0, 0);
  for (int s = 0; s < 8; s++) {
    const int buf = s & 1;
    if (s < 7) { issue(s + 1, buf ^ 1); cp_wait1(); } else { cp_wait0(); }
    __syncthreads();
    const unsigned* Ar = reinterpret_cast<const unsigned*>(Abuf[buf]);
    const unsigned* Wr = reinterpret_cast<const unsigned*>(Wbuf[buf]);
#pragma unroll
    for (int k16 = 0; k16 < 4; k16++) {
      const int kw = k16 * 8;
      unsigned a[2][4], b[4][2];
#pragma unroll
      for (int mi = 0; mi < 2; mi++) {
        const int rr = wm * 32 + mi * 16 + g;
        a[mi][0] = Ar[rr * 36 + kw + t4];       a[mi][1] = Ar[(rr + 8) * 36 + kw + t4];
        a[mi][2] = Ar[rr * 36 + kw + 4 + t4];   a[mi][3] = Ar[(rr + 8) * 36 + kw + 4 + t4];
      }
#pragma unroll
      for (int ni = 0; ni < 4; ni++) {
        const int cc = wn * 32 + ni * 8 + g;
        b[ni][0] = Wr[cc * 36 + kw + t4]; b[ni][1] = Wr[cc * 36 + kw + 4 + t4];
      }
#pragma unroll
      for (int mi = 0; mi < 2; mi++)
#pragma unroll
        for (int ni = 0; ni < 4; ni++) mma_f16(c[mi][ni], a[mi], b[ni]);
    }
    __syncthreads();
  }

  if (MODE == 0 && z == 2) {
    // stage transposed in smem, then coalesced store to g_VhT
    __half* Vst = psm;  // [64][136]
#pragma unroll
    for (int mi = 0; mi < 2; mi++)
#pragma unroll
      for (int ni = 0; ni < 4; ni++)
#pragma unroll
        for (int hf = 0; hf < 2; hf++) {
          const int rl = wm * 32 + mi * 16 + g + hf * 8;
          const int d = wn * 32 + ni * 8 + t4 * 2;
          Vst[d * 136 + rl]       = __float2half_rn(c[mi][ni][hf * 2 + 0] + bias[n0 + d]);
          Vst[(d + 1) * 136 + rl] = __float2half_rn(c[mi][ni][hf * 2 + 1] + bias[n0 + d + 1]);
        }
    __syncthreads();
    const int d = tid >> 2, q32 = tid & 3;
    const uint4* srcp = reinterpret_cast<const uint4*>(Vst + d * 136 + q32 * 32);
    __half* dstp = g_VhT + (size_t)((bbM * NH + (n0 >> 6)) * DK + d) * S + ii0 + q32 * 32;
#pragma unroll
    for (int i = 0; i < 4; i++) reinterpret_cast<uint4*>(dstp)[i] = srcp[i];
    return;
  }

#pragma unroll
  for (int mi = 0; mi < 2; mi++)
#pragma unroll
    for (int ni = 0; ni < 4; ni++)
#pragma unroll
      for (int hf = 0; hf < 2; hf++) {
        const int row = m0 + wm * 32 + mi * 16 + g + hf * 8;
        const int col = n0 + wn * 32 + ni * 8 + t4 * 2;
        const float v0 = c[mi][ni][hf * 2 + 0] + bias[col];
        const float v1 = c[mi][ni][hf * 2 + 1] + bias[col + 1];
        if (MODE == 1) {
          *reinterpret_cast<float2*>(&Cout[row * 512 + col]) = make_float2(v0, v1);
        } else {
          const int bb = row >> 9, ii = row & 511, h = col >> 6, d = col & 63;
          __half* dst = (z == 0) ? g_Qh : g_Kh;
          *reinterpret_cast<__half2*>(&dst[(((bb * NH + h) * S) + ii) * DK + d]) =
              __floats2half2_rn(v0, v1);
        }
      }
}

// ---------------- tables: QHop/KHop/EB via fp16 mma ---------------------------
__global__ __launch_bounds__(256) void tables_mma(
    const float* __restrict__ qhe, const float* __restrict__ qee,
    const float* __restrict__ khe, const float* __restrict__ kee) {
  __shared__ unsigned Qs[64][36];
  __shared__ unsigned Ks2[64][36];
  __shared__ unsigned Eq[48][36];
  __shared__ unsigned Ek[48][36];
  const int bh = blockIdx.x, h = bh & 7;
  const int i0 = blockIdx.y * 64;
  const int tid = threadIdx.x;
  const int lane = tid & 31, wid = tid >> 5;
  const int wm = wid & 3, wn = wid >> 2;
  const int g = lane >> 2, t4 = lane & 3;

  for (int i = tid; i < 64 * 16; i += 256) {
    const int r = i >> 4, u = i & 15;
    uint2 q = *reinterpret_cast<const uint2*>(&g_Qh[(bh * S + i0 + r) * DK + u * 4]);
    uint2 k = *reinterpret_cast<const uint2*>(&g_Kh[(bh * S + i0 + r) * DK + u * 4]);
    Qs[r][u * 2] = q.x;  Qs[r][u * 2 + 1] = q.y;
    Ks2[r][u * 2] = k.x; Ks2[r][u * 2 + 1] = k.y;
  }
  for (int i = tid; i < 48 * 16; i += 256) {
    const int r = i >> 4, cc = (i & 15) * 4;
    const float* sq = (r < TH) ? &qhe[r * HID + h * DK + cc] : &qee[(r - TH) * HID + h * DK + cc];
    const float* sk = (r < TH) ? &khe[r * HID + h * DK + cc] : &kee[(r - TH) * HID + h * DK + cc];
    float4 vq = *reinterpret_cast<const float4*>(sq);
    float4 vk = *reinterpret_cast<const float4*>(sk);
    Eq[r][(cc >> 1)]     = pack_half2(vq.x, vq.y);
    Eq[r][(cc >> 1) + 1] = pack_half2(vq.z, vq.w);
    Ek[r][(cc >> 1)]     = pack_half2(vk.x, vk.y);
    Ek[r][(cc >> 1) + 1] = pack_half2(vk.z, vk.w);
  }
  __syncthreads();

  float cQ[3][4] = {}, cK[3][4] = {};
#pragma unroll
  for (int ks = 0; ks < 4; ks++) {
    const int kw = ks * 8;
    const int rr = wm * 16 + g;
    unsigned aQ[4], aK[4], bQ[3][2], bK[3][2];
    aQ[0] = Qs[rr][kw + t4];      aQ[1] = Qs[rr + 8][kw + t4];
    aQ[2] = Qs[rr][kw + 4 + t4];  aQ[3] = Qs[rr + 8][kw + 4 + t4];
    aK[0] = Ks2[rr][kw + t4];     aK[1] = Ks2[rr + 8][kw + t4];
    aK[2] = Ks2[rr][kw + 4 + t4]; aK[3] = Ks2[rr + 8][kw + 4 + t4];
#pragma unroll
    for (int ni = 0; ni < 3; ni++) {
      const int cc = wn * 24 + ni * 8 + g;
      bQ[ni][0] = Eq[cc][kw + t4]; bQ[ni][1] = Eq[cc][kw + 4 + t4];
      bK[ni][0] = Ek[cc][kw + t4]; bK[ni][1] = Ek[cc][kw + 4 + t4];
    }
#pragma unroll
    for (int ni = 0; ni < 3; ni++) {
      mma_f16(cQ[ni], aQ, bQ[ni]);
      mma_f16(cK[ni], aK, bK[ni]);
    }
  }
#pragma unroll
  for (int ni = 0; ni < 3; ni++)
#pragma unroll
    for (int fi = 0; fi < 4; fi++) {
      const int row = i0 + wm * 16 + g + ((fi >= 2) ? 8 : 0);
      const int col = wn * 24 + ni * 8 + t4 * 2 + (fi & 1);
      if (col < TH) {
        g_QHop[(bh * S + row) * TH + col] = cQ[ni][fi];
        g_KHop[(bh * S + row) * TH + col] = cK[ni][fi];
      } else {
        g_EB[(bh * S + row) * TE + (col - TH)] = cQ[ni][fi] + cK[ni][fi];
      }
    }
}

// ---------------- fused flash attention + bins (no online max) ----------------
struct FSmem {
  unsigned Qs[64][36];
  unsigned Ks[128][36];
  unsigned Vt[64][68];       // V^T chunk [d][j]; tables in epilogue
  unsigned Ph[64][68];       // half P; normalized bins in epilogue
  __half KHs[128][40];
  float rowhop[64][32];
  float rowedge[64][16];
  float binsH[64][32];
  float binsE[64][16];
  float rowl[64];
  unsigned short de[64][128];
};

__global__ __launch_bounds__(512) void fused_attn(
    const float* __restrict__ vhe, const float* __restrict__ vee) {
  extern __shared__ char smem_raw[];
  FSmem& sm = *reinterpret_cast<FSmem*>(smem_raw);
  const int bh = blockIdx.x, b = bh >> 3, h = bh & 7;
  const int i0 = blockIdx.y * 64;
  const int tid = threadIdx.x;
  const int lane = tid & 31, wid = tid >> 5;
  const int g = lane >> 2, t4 = lane & 3;
  const int wmq = wid & 3, wnq = wid >> 2;  // QK: 16 x 32
  const int wma = wid & 3, wna = wid >> 2;  // AV: 16 x 16

  for (int i = tid; i < 64 * 16; i += 512) {
    const int r = i >> 4, u = i & 15;
    uint2 q = *reinterpret_cast<const uint2*>(&g_Qh[(bh * S + i0 + r) * DK + u * 4]);
    sm.Qs[r][u * 2] = q.x; sm.Qs[r][u * 2 + 1] = q.y;
  }
  for (int i = tid; i < 64 * 8; i += 512) {
    const int r = i >> 3, cc = (i & 7) * 4;
    *reinterpret_cast<float4*>(&sm.rowhop[r][cc]) =
        *reinterpret_cast<const float4*>(&g_QHop[(bh * S + i0 + r) * TH + cc]);
  }
  for (int i = tid; i < 64 * 4; i += 512) {
    const int r = i >> 2, cc = (i & 3) * 4;
    *reinterpret_cast<float4*>(&sm.rowedge[r][cc]) =
        *reinterpret_cast<const float4*>(&g_EB[(bh * S + i0 + r) * TE + cc]);
  }
  for (int i = tid; i < 64 * 32; i += 512) sm.binsH[i >> 5][i & 31] = 0.f;
  for (int i = tid; i < 64 * 16; i += 512) sm.binsE[i >> 4][i & 15] = 0.f;
  if (tid < 64) sm.rowl[tid] = 0.f;

  float co[2][4] = {};
  const int rrq = wmq * 16 + g;
  const int rra = wma * 16 + g;

  for (int ch = 0; ch < 4; ch++) {
    const int j0 = ch * 128;
    for (int i = tid; i < 128 * 16; i += 512) {
      const int r = i >> 4, u = i & 15;
      uint2 k = *reinterpret_cast<const uint2*>(&g_Kh[(bh * S + j0 + r) * DK + u * 4]);
      sm.Ks[r][u * 2] = k.x; sm.Ks[r][u * 2 + 1] = k.y;
    }
    for (int i = tid; i < 64 * 32; i += 512) {
      const int d = i >> 5, u = i & 31;
      uint2 v = *reinterpret_cast<const uint2*>(&g_VhT[(size_t)(bh * DK + d) * S + j0 + u * 4]);
      sm.Vt[d][u * 2] = v.x; sm.Vt[d][u * 2 + 1] = v.y;
    }
    for (int i = tid; i < 128 * 8; i += 512) {
      const int r = i >> 3, cc = (i & 7) * 4;
      float4 v = *reinterpret_cast<const float4*>(&g_KHop[(bh * S + j0 + r) * TH + cc]);
      *reinterpret_cast<__half2*>(&sm.KHs[r][cc])     = __floats2half2_rn(v.x, v.y);
      *reinterpret_cast<__half2*>(&sm.KHs[r][cc + 2]) = __floats2half2_rn(v.z, v.w);
    }
    for (int i = tid; i < 64 * 16; i += 512) {
      const int r = i >> 4, c8 = (i & 15) * 8;
      const size_t base = ((size_t)b * S + i0 + r) * S + j0 + c8;
      *reinterpret_cast<uint4*>(&sm.de[r][c8]) =
          *reinterpret_cast<const uint4*>(&g_DE16[base]);
    }
    __syncthreads();

    // ---- QK mma ----
    float cq[4][4] = {};
#pragma unroll
    for (int ks = 0; ks < 4; ks++) {
      const int kw = ks * 8;
      unsigned a[4], bf[4][2];
      a[0] = sm.Qs[rrq][kw + t4];     a[1] = sm.Qs[rrq + 8][kw + t4];
      a[2] = sm.Qs[rrq][kw + 4 + t4]; a[3] = sm.Qs[rrq + 8][kw + 4 + t4];
#pragma unroll
      for (int ni = 0; ni < 4; ni++) {
        const int jl = wnq * 32 + ni * 8 + g;
        bf[ni][0] = sm.Ks[jl][kw + t4]; bf[ni][1] = sm.Ks[jl][kw + 4 + t4];
      }
#pragma unroll
      for (int ni = 0; ni < 4; ni++) mma_f16(cq[ni], a, bf[ni]);
    }

    // ---- fused epilogue: bias gather + exp2 + bins + row sums + P(half) ----
    {
      const int r0 = wmq * 16 + g, r1 = r0 + 8;
      __half* ph0 = reinterpret_cast<__half*>(&sm.Ph[r0][0]);
      __half* ph1 = reinterpret_cast<__half*>(&sm.Ph[r1][0]);
      float s0 = 0.f, s1 = 0.f;
#pragma unroll
      for (int ni = 0; ni < 4; ni++)
#pragma unroll
        for (int fi = 0; fi < 4; fi++) {
          const bool hi = (fi >= 2);
          const int row = hi ? r1 : r0;
          const int jl = wnq * 32 + ni * 8 + t4 * 2 + (fi & 1);
          const unsigned de = sm.de[row][jl];
          const int dh = de & 0xFF, ee = de >> 8;
          const float score =
              (cq[ni][fi] + sm.rowhop[row][dh] + __half2float(sm.KHs[jl][dh]) +
               sm.rowedge[row][ee]) * SC2;
          const float p = fast_exp2(score);
          (hi ? ph1 : ph0)[jl] = __float2half_rn(p);
          atomicAdd(&sm.binsH[row][dh], p);
          atomicAdd(&sm.binsE[row][ee], p);
          if (hi) s1 += p; else s0 += p;
        }
      atomicAdd(&sm.rowl[r0], s0);
      atomicAdd(&sm.rowl[r1], s1);
    }
    __syncthreads();

    // ---- P@V mma (no rescale) ----
#pragma unroll
    for (int ks = 0; ks < 8; ks++) {
      const int kw = ks * 8;
      unsigned a[4], bf[2][2];
      a[0] = sm.Ph[rra][kw + t4];     a[1] = sm.Ph[rra + 8][kw + t4];
      a[2] = sm.Ph[rra][kw + 4 + t4]; a[3] = sm.Ph[rra + 8][kw + 4 + t4];
#pragma unroll
      for (int ni = 0; ni < 2; ni++) {
        const int cc = wna * 16 + ni * 8 + g;
        bf[ni][0] = sm.Vt[cc][kw + t4]; bf[ni][1] = sm.Vt[cc][kw + 4 + t4];
      }
#pragma unroll
      for (int ni = 0; ni < 2; ni++) mma_f16(co[ni], a, bf[ni]);
    }
    __syncthreads();
  }

  // ---- epilogue: normalize O, add normalized-bins GEMMs, store ----
  const float inv0 = 1.f / sm.rowl[rra];
  const float inv1 = 1.f / sm.rowl[rra + 8];
#pragma unroll
  for (int ni = 0; ni < 2; ni++) {
    co[ni][0] *= inv0; co[ni][1] *= inv0;
    co[ni][2] *= inv1; co[ni][3] *= inv1;
  }
  for (int i = tid; i < 64 * 48; i += 512) {
    const int r = i / 48, t = i % 48;
    const float invr = 1.f / sm.rowl[r];
    const float v = ((t < TH) ? sm.binsH[r][t] : sm.binsE[r][t - TH]) * invr;
    reinterpret_cast<__half*>(&sm.Ph[r][0])[t] = __float2half_rn(v);
  }
  for (int i = tid; i < 64 * 24; i += 512) {
    const int d = i / 24, tw = i % 24;
    const int t0 = tw * 2, t1 = t0 + 1;
    const float x = (t0 < TH) ? vhe[t0 * HID + h * DK + d] : vee[(t0 - TH) * HID + h * DK + d];
    const float y = (t1 < TH) ? vhe[t1 * HID + h * DK + d] : vee[(t1 - TH) * HID + h * DK + d];
    sm.Vt[d][tw] = pack_half2(x, y);
  }
  __syncthreads();
#pragma unroll
  for (int ks = 0; ks < 3; ks++) {
    const int kw = ks * 8;
    unsigned a[4], bf[2][2];
    a[0] = sm.Ph[rra][kw + t4];     a[1] = sm.Ph[rra + 8][kw + t4];
    a[2] = sm.Ph[rra][kw + 4 + t4]; a[3] = sm.Ph[rra + 8][kw + 4 + t4];
#pragma unroll
    for (int ni = 0; ni < 2; ni++) {
      const int cc = wna * 16 + ni * 8 + g;
      bf[ni][0] = sm.Vt[cc][kw + t4]; bf[ni][1] = sm.Vt[cc][kw + 4 + t4];
    }
#pragma unroll
    for (int ni = 0; ni < 2; ni++) mma_f16(co[ni], a, bf[ni]);
  }

#pragma unroll
  for (int ni = 0; ni < 2; ni++) {
    const int col = wna * 16 + ni * 8 + t4 * 2;
    const int row0 = i0 + wma * 16 + g;
    *reinterpret_cast<__half2*>(&g_OutH[(bh * S + row0) * DK + col]) =
        __floats2half2_rn(co[ni][0], co[ni][1]);
    *reinterpret_cast<__half2*>(&g_OutH[(bh * S + row0 + 8) * DK + col]) =
        __floats2half2_rn(co[ni][2], co[ni][3]);
  }
}

// ---------------- launcher ----------------------------------------------------
extern "C" void kernel_launch(void* const* d_in, const int* in_sizes, int n_in,
                              void* d_out, int out_size) {
  (void)in_sizes; (void)n_in; (void)out_size;
  const float* q   = (const float*)d_in[0];
  const float* k   = (const float*)d_in[1];
  const float* v   = (const float*)d_in[2];
  const float* qhe = (const float*)d_in[3];
  const float* qee = (const float*)d_in[4];
  const float* khe = (const float*)d_in[5];
  const float* kee = (const float*)d_in[6];
  const float* vhe = (const float*)d_in[7];
  const float* vee = (const float*)d_in[8];
  const int* dist  = (const int*)d_in[9];
  const int* edge  = (const int*)d_in[10];
  const float* Wq = (const float*)d_in[11], *bq = (const float*)d_in[12];
  const float* Wk = (const float*)d_in[13], *bk = (const float*)d_in[14];
  const float* Wv = (const float*)d_in[15], *bv = (const float*)d_in[16];
  const float* Wo = (const float*)d_in[17], *bo = (const float*)d_in[18];
  float* out = (float*)d_out;

  const int proj_smem = (2 * 128 * 72 + 2 * 64 * 72) * 2;  // 55296
  const int fused_smem = (int)sizeof(FSmem);
  cudaFuncSetAttribute(proj_mma<0>, cudaFuncAttributeMaxDynamicSharedMemorySize, proj_smem);
  cudaFuncSetAttribute(proj_mma<1>, cudaFuncAttributeMaxDynamicSharedMemorySize, proj_smem);
  cudaFuncSetAttribute(fused_attn, cudaFuncAttributeMaxDynamicSharedMemorySize, fused_smem);

  const int QU = QN / 8, WU = WN / 8;
  const int cv_total = 3 * QU + 4 * WU;
  convert_kernel<<<(cv_total + 255) / 256, 256>>>(q, k, v, Wq, Wk, Wv, Wo);
  const size_t n4 = (size_t)B * S * S / 4;
  pack_kernel<<<(int)((n4 + 255) / 256), 256>>>(dist, edge);

  proj_mma<0><<<dim3(8, 64, 3), 256, proj_smem>>>(bq, bk, bv, nullptr);
  tables_mma<<<dim3(BH, 8), 256>>>(qhe, qee, khe, kee);
  fused_attn<<<dim3(BH, 8), 512, fused_smem>>>(vhe, vee);
  proj_mma<1><<<dim3(8, 64, 1), 256, proj_smem>>>(bo, nullptr, nullptr, out);
}